// round 11
// baseline (speedup 1.0000x reference)
#include <cuda_runtime.h>
#include <cuda_bf16.h>
#include <cstdint>

#define Bn 128
#define Tn 256
#define NHID 1024
#define NIN 128
#define NOUT 64
#define KTOT 1152
#define NCOMPUTE 128
#define NHELPER 16
#define NCTA (NCOMPUTE + NHELPER)    // 144
#define THREADS 512
#define JSL 32          // j per compute CTA
#define GRPN 36         // CTAs per barrier group (32 compute + 4 helpers)

// output layout: hidden_list [128][256][1024] ++ output_list [128][256][64] ++ h_final [128][1024]
#define OUT_HID 0
#define OUT_OUT 33554432
#define OUT_HF  35651584

// -------- device scratch --------
__device__ float g_act[2][NHID * Bn];       // tanh(h) [k][b], double buffered
__device__ float g_xT[Tn * NIN * Bn];       // x transposed [t][i][b]
__device__ float g_h[3][Bn * NHID];         // h[t] [b][j], triple buffered
__device__ unsigned g_arrive4[128];         // per-bg barrier counters (stride 32)
__device__ unsigned g_release4[128];

typedef unsigned long long ull;

__device__ __forceinline__ ull pack2(float x) {
    ull r; asm("mov.b64 %0, {%1, %1};" : "=l"(r) : "f"(x)); return r;
}
__device__ __forceinline__ void fma2(ull& c, ull a, ull b) {
    asm("fma.rn.f32x2 %0, %1, %2, %0;" : "+l"(c) : "l"(a), "l"(b));
}
__device__ __forceinline__ float2 unpack2(ull v) {
    float2 f; asm("mov.b64 {%0, %1}, %2;" : "=f"(f.x), "=f"(f.y) : "l"(v)); return f;
}
__device__ __forceinline__ void cpasync16(uint32_t dst, const float* src) {
    asm volatile("cp.async.cg.shared.global [%0], [%1], 16;" :: "r"(dst), "l"(src));
}
__device__ __forceinline__ void cpcommit() { asm volatile("cp.async.commit_group;"); }
template<int N> __device__ __forceinline__ void cpwait() {
    asm volatile("cp.async.wait_group %0;" :: "n"(N));
}
__device__ __forceinline__ float4 ldcg4(const float* p) {
    float4 v;
    asm volatile("ld.global.cg.v4.f32 {%0,%1,%2,%3}, [%4];"
                 : "=f"(v.x), "=f"(v.y), "=f"(v.z), "=f"(v.w) : "l"(p));
    return v;
}

// fast exact-formula tanh: 1 - 2/(exp(2x)+1) via MUFU
__device__ __forceinline__ float fast_tanh(float x) {
    float e;
    asm("ex2.approx.f32 %0, %1;" : "=f"(e) : "f"(x * 2.8853900817779268f));
    float r;
    asm("rcp.approx.f32 %0, %1;" : "=f"(r) : "f"(e + 1.0f));
    return __fmaf_rn(-2.0f, r, 1.0f);
}

// -------- x transpose: g_xT[t][i][b] = input_signal[b][t][i] --------
__global__ void xT_kernel(const float* __restrict__ in) {
    __shared__ float s[128][33];
    int t = blockIdx.x >> 2, ig = blockIdx.x & 3;
    for (int idx = threadIdx.x; idx < 128 * 32; idx += 256) {
        int b = idx >> 5, ii = idx & 31;
        s[b][ii] = in[b * (Tn * NIN) + t * NIN + ig * 32 + ii];
    }
    __syncthreads();
    for (int idx = threadIdx.x; idx < 4096; idx += 256) {
        int ii = idx >> 7, b = idx & 127;
        g_xT[t * (NIN * Bn) + (ig * 32 + ii) * Bn + b] = s[b][ii];
    }
}

// -------- smem layout (float offsets), compute role --------
#define SM_W    0                       // [1152][32] weights ([k][j])
#define SM_ACT  (SM_W + KTOT * 32)      // act_w[16][3][256] private rings (red aliases)
#define SM_TJ   (SM_ACT + 16 * 768)     // tanh(h) [j][b] [32][36]
#define SM_FLOATS (SM_TJ + 32 * 36)     // = 50304 floats
#define SMEM_BYTES (SM_FLOATS * 4)
// helper role reuses same smem: ws [1024][32] (32768) + hs [16][1024] (16384)
// + hred (1024 floats) = 50176 <= 50304

#define GRIDBAR() do {                                                        \
        __threadfence();                                                      \
        __syncthreads();                                                      \
        if (tid == 0) {                                                       \
            bar_t += (unsigned)GRPN;                                          \
            unsigned a_ = atomicAdd(&g_arrive4[bg * 32], 1u) + 1u;            \
            if (a_ == bar_t) { atomicExch(&g_release4[bg * 32], bar_t); }     \
            else { while ((int)(*((volatile unsigned*)&g_release4[bg * 32]) - bar_t) < 0) {} } \
        }                                                                     \
        __syncthreads();                                                      \
    } while (0)

__global__ void __launch_bounds__(THREADS, 1)
rnn_main(const float* __restrict__ hidden,
         const float* __restrict__ w_in,
         const float* __restrict__ w_hh,
         const float* __restrict__ w_b,
         const float* __restrict__ w_out,
         const float* __restrict__ alpha,
         const float* __restrict__ noise,
         const int* __restrict__ ptp,
         float* __restrict__ out)
{
    extern __shared__ float sm[];
    const int tid = threadIdx.x;
    const int cta = blockIdx.x;

    if (cta < NCOMPUTE) {
        // ==================== COMPUTE ROLE ====================
        float* w_s   = sm + SM_W;
        float* act_s = sm + SM_ACT;
        float* red   = act_s;               // alias: [8][32][36] = 9216 <= 12288 floats
        float* tj    = sm + SM_TJ;

        const int jg = cta & 31, bg = cta >> 5;
        const int jbase = jg * JSL, bbase = bg * 32;

        const int w   = tid >> 5;       // warp 0..15 : owns rows w*8..w*8+7 per chunk
        const int lid = tid & 31;
        const int bq  = lid & 7;
        const int jq  = lid >> 3;
        const int b0  = bq * 4;
        const int j0  = jq * 8;

        // ---- weights into smem [k][32j] (once) ----
        {
            int jj = tid >> 4;
            int kk = tid & 15;
            const float* wr = w_hh + (size_t)(jbase + jj) * NHID;
            for (int k = kk; k < NHID; k += 16)
                w_s[k * 32 + jj] = wr[k];
            const float* wi = w_in + (size_t)(jbase + jj) * NIN;
            for (int i = kk; i < NIN; i += 16)
                w_s[(NHID + i) * 32 + jj] = wi[i];
        }

        // ---- per-thread h ownership: bloc = tid>>4, j = jp, jp+1 ----
        const int bloc = tid >> 4;
        const int jp = (tid & 15) * 2;
        const int bown = bbase + bloc;

        float2 al2 = *(const float2*)&alpha[jbase + jp];
        float2 bi2 = *(const float2*)&w_b[jbase + jp];
        float2 ns2 = make_float2(0.05f * sqrtf(al2.x), 0.05f * sqrtf(al2.y));
        const int pt = *ptp;

        float2 hv = *(const float2*)&hidden[(size_t)bown * NHID + jbase + jp];
        float h0 = hv.x, h1 = hv.y;

        g_act[0][(jbase + jp) * Bn + bown]     = fast_tanh(h0);
        g_act[0][(jbase + jp + 1) * Bn + bown] = fast_tanh(h1);

        unsigned bar_t = 0;
        if (tid == 0) bar_t = *((volatile unsigned*)&g_release4[bg * 32]);

        // warp-private act ring: act_w[w][3][256]
        const uint32_t actw_u = (uint32_t)__cvta_generic_to_shared(act_s) + (uint32_t)(w * 768 * 4);
        const float* actw = act_s + w * 768;
        const int srow = lid >> 2;
        const int scol = (lid & 3) * 8;

#define WSTAGE(BASE, SLOT) do {                                               \
        const float* _s = (BASE) + (w * 8 + srow) * Bn + bbase + scol;        \
        uint32_t _d = actw_u + (uint32_t)(((SLOT) * 256 + srow * 32 + scol) * 4); \
        cpasync16(_d,      _s);                                               \
        cpasync16(_d + 16, _s + 4);                                           \
        cpcommit();                                                           \
    } while (0)

        // pre-stage item0 of step 0 (x chunk) into slot 0
        WSTAGE(g_xT, 0);

        GRIDBAR();   // g_act[0] visible

        for (int t = 0; t < Tn; t++) {
            const float* asrc = g_act[t & 1];

            // prologue: stage item1 (= act chunk 0) into slot 1
            WSTAGE(asrc, 1);

            ull acc[4][4];
            #pragma unroll
            for (int i = 0; i < 4; i++)
                #pragma unroll
                for (int j = 0; j < 4; j++) acc[i][j] = 0;

            // ---- GEMM: item order [x-chunk(8), act chunks 0..7]; warps free-run ----
            #pragma unroll 1
            for (int n = 0; n < 9; n++) {
                if (n <= 6) {
                    WSTAGE(asrc + (n + 1) * 128 * Bn, (n + 2) % 3);
                    cpwait<2>();
                } else if (n == 7) {
                    cpwait<1>();
                } else {
                    cpwait<0>();
                }
                __syncwarp();

                const int kc = (n == 0) ? 8 : (n - 1);
                const float* abk = actw + (n % 3) * 256 + b0;
                const float* wbk = w_s + (kc * 128 + w * 8) * 32 + j0;
                #pragma unroll
                for (int i = 0; i < 8; i++) {
                    float4 av = *(const float4*)(abk + i * 32);
                    ulonglong2 w01 = *(const ulonglong2*)(wbk + i * 32);
                    ulonglong2 w23 = *(const ulonglong2*)(wbk + i * 32 + 4);
                    ull a0 = pack2(av.x), a1 = pack2(av.y);
                    ull a2 = pack2(av.z), a3 = pack2(av.w);
                    fma2(acc[0][0], a0, w01.x); fma2(acc[0][1], a0, w01.y);
                    fma2(acc[0][2], a0, w23.x); fma2(acc[0][3], a0, w23.y);
                    fma2(acc[1][0], a1, w01.x); fma2(acc[1][1], a1, w01.y);
                    fma2(acc[1][2], a1, w23.x); fma2(acc[1][3], a1, w23.y);
                    fma2(acc[2][0], a2, w01.x); fma2(acc[2][1], a2, w01.y);
                    fma2(acc[2][2], a2, w23.x); fma2(acc[2][3], a2, w23.y);
                    fma2(acc[3][0], a3, w01.x); fma2(acc[3][1], a3, w01.y);
                    fma2(acc[3][2], a3, w23.x); fma2(acc[3][3], a3, w23.y);
                }
            }
            __syncthreads();   // act rings free (red aliases them)

            // ---- 16-way k-split reduce, deterministic ----
            if (w >= 8) {
                float* rd = red + (w - 8) * (32 * 36);
                #pragma unroll
                for (int bb = 0; bb < 4; bb++) {
                    float2 v0 = unpack2(acc[bb][0]);
                    float2 v1 = unpack2(acc[bb][1]);
                    float2 v2 = unpack2(acc[bb][2]);
                    float2 v3 = unpack2(acc[bb][3]);
                    *(float4*)(rd + (b0 + bb) * 36 + j0)     = make_float4(v0.x, v0.y, v1.x, v1.y);
                    *(float4*)(rd + (b0 + bb) * 36 + j0 + 4) = make_float4(v2.x, v2.y, v3.x, v3.y);
                }
            }
            __syncthreads();
            if (w < 8) {
                float* rd = red + w * (32 * 36);
                #pragma unroll
                for (int bb = 0; bb < 4; bb++) {
                    float4 p0 = *(const float4*)(rd + (b0 + bb) * 36 + j0);
                    float4 p1 = *(const float4*)(rd + (b0 + bb) * 36 + j0 + 4);
                    float2 v0 = unpack2(acc[bb][0]);
                    float2 v1 = unpack2(acc[bb][1]);
                    float2 v2 = unpack2(acc[bb][2]);
                    float2 v3 = unpack2(acc[bb][3]);
                    *(float4*)(rd + (b0 + bb) * 36 + j0) =
                        make_float4(v0.x + p0.x, v0.y + p0.y, v1.x + p0.z, v1.y + p0.w);
                    *(float4*)(rd + (b0 + bb) * 36 + j0 + 4) =
                        make_float4(v2.x + p1.x, v2.y + p1.y, v3.x + p1.z, v3.y + p1.w);
                }
            }
            __syncthreads();

            // ---- 8-way reduce + h update ----
            {
                float s0 = bi2.x, s1 = bi2.y;
                #pragma unroll
                for (int g = 0; g < 8; g++) {
                    float2 v = *(const float2*)(red + g * (32 * 36) + bloc * 36 + jp);
                    s0 += v.x; s1 += v.y;
                }
                h0 = (1.f - al2.x) * h0 + al2.x * s0;
                h1 = (1.f - al2.y) * h1 + al2.y * s1;
                if (t == pt) {
                    float2 n = *(const float2*)&noise[(size_t)bown * NHID + jbase + jp];
                    h0 += n.x * ns2.x;
                    h1 += n.y * ns2.y;
                }
            }

            // h -> g_h (coalesced float2); tanh -> tj
            *(float2*)&g_h[t % 3][(size_t)bown * NHID + jbase + jp] = make_float2(h0, h1);
            tj[(jp)     * 36 + bloc] = fast_tanh(h0);
            tj[(jp + 1) * 36 + bloc] = fast_tanh(h1);
            __syncthreads();     // red reads done -> ring slot 0 reusable; tj ready

            // next act buffer write (all 512 threads, float2; row = local j)
            {
                int rw = tid >> 4, q = (tid & 15) * 2;
                float2 a = *(const float2*)(tj + rw * 36 + q);
                *(float2*)&g_act[(t + 1) & 1][(jbase + rw) * Bn + bbase + q] = a;
            }

            // pre-stage next step's x chunk into ring slot 0
            if (t + 1 < Tn)
                WSTAGE(g_xT + (t + 1) * (NIN * Bn), 0);

            GRIDBAR();
        }
#undef WSTAGE
    } else {
        // ==================== HELPER ROLE ====================
        const int idx = cta - NCOMPUTE;
        const int bg = idx >> 2;
        const int bh = (idx >> 1) & 1;
        const int oh = idx & 1;
        const int b2 = bg * 32 + bh * 16;     // 16 b rows
        const int obase = oh * 32;            // 32 outputs

        float* ws   = sm;                      // [1024][32]  w_out slice (o contiguous)
        float* hs   = sm + 32768;              // [16][1024]  h rows
        float* hred = sm + 49152;              // [16][16][2] float2 partials (1024 floats)

        // load w_out slice (once)
        for (int i = tid; i < 32 * 1024; i += THREADS) {
            int o = i >> 10, k = i & 1023;
            ws[k * 32 + o] = w_out[(size_t)(obase + o) * NHID + k];
        }

        unsigned bar_t = 0;
        if (tid == 0) bar_t = *((volatile unsigned*)&g_release4[bg * 32]);

        GRIDBAR();

        // out-GEMM mapping: 16 b-rows x 16 o-pairs x 2 k-halves = 512 threads
        const int gb = (tid >> 4) & 15;   // b row 0..15
        const int po = tid & 15;          // o-pair 0..15 (2 outputs each)
        const int kh = tid >> 8;          // k-half 0/1
        const int kb = kh * 512;          // k base

        for (int t = 0; t <= Tn; t++) {
            if (t > 0) {
                const int tt = t - 1;
                // ---- load h rows [16][1024] from g_h (L2 reads) ----
                const float* gh = g_h[tt % 3] + (size_t)b2 * NHID;
                #pragma unroll
                for (int i = 0; i < 8; i++) {
                    int i4 = tid + i * THREADS;            // 4096 float4 total
                    int r = i4 >> 8, c = (i4 & 255) * 4;
                    float4 v = ldcg4(gh + (size_t)r * NHID + c);
                    *(float4*)&hs[r * 1024 + c] = v;
                }
                __syncthreads();

                // ---- hidden_list (+h_final) write: rows oh*8 .. oh*8+7 ----
                #pragma unroll
                for (int i = 0; i < 4; i++) {
                    int i4 = tid + i * THREADS;            // 2048 float4 total
                    int r = oh * 8 + (i4 >> 8);
                    int c = (i4 & 255) * 4;
                    float4 v = *(const float4*)&hs[r * 1024 + c];
                    *(float4*)&out[OUT_HID + (size_t)(b2 + r) * (Tn * NHID)
                                   + (size_t)tt * NHID + c] = v;
                    if (tt == Tn - 1)
                        *(float4*)&out[OUT_HF + (size_t)(b2 + r) * NHID + c] = v;
                }

                // ---- out GEMM half-K: acc over k in [kb, kb+512) ----
                {
                    const float* ha = hs + gb * 1024 + kb;
                    const ull* wu = (const ull*)ws + (size_t)kb * 16 + po;
                    ull acc = 0;
                    #pragma unroll 8
                    for (int k = 0; k < 512; k += 4) {
                        float4 a4 = *(const float4*)(ha + k);
                        fma2(acc, pack2(a4.x), wu[(k + 0) * 16]);
                        fma2(acc, pack2(a4.y), wu[(k + 1) * 16]);
                        fma2(acc, pack2(a4.z), wu[(k + 2) * 16]);
                        fma2(acc, pack2(a4.w), wu[(k + 3) * 16]);
                    }
                    float2 p = unpack2(acc);
                    *(float2*)&hred[((gb * 16 + po) * 2 + kh) * 2] = p;
                }
                __syncthreads();

                // combine k-halves (deterministic order) and store
                if (kh == 0) {
                    float2 p0 = *(const float2*)&hred[((gb * 16 + po) * 2 + 0) * 2];
                    float2 p1 = *(const float2*)&hred[((gb * 16 + po) * 2 + 1) * 2];
                    float2 o2 = make_float2(p0.x + p1.x, p0.y + p1.y);
                    *(float2*)&out[OUT_OUT + (size_t)(b2 + gb) * (Tn * NOUT)
                                   + (size_t)tt * NOUT + obase + po * 2] = o2;
                }
                __syncthreads();
            }
            if (t < Tn) GRIDBAR();
        }
    }
}
#undef GRIDBAR

// -------- launcher --------
extern "C" void kernel_launch(void* const* d_in, const int* in_sizes, int n_in,
                              void* d_out, int out_size)
{
    const float* input_signal = (const float*)d_in[0];
    const float* hidden       = (const float*)d_in[1];
    const float* w_in_w       = (const float*)d_in[2];
    const float* w_hh_w       = (const float*)d_in[3];
    const float* w_hh_b       = (const float*)d_in[4];
    const float* w_out_w      = (const float*)d_in[5];
    const float* alpha        = (const float*)d_in[6];
    const float* noise_raw    = (const float*)d_in[7];
    const int*   pt           = (const int*)d_in[8];
    float* out = (float*)d_out;

    cudaFuncSetAttribute(rnn_main, cudaFuncAttributeMaxDynamicSharedMemorySize, SMEM_BYTES);

    xT_kernel<<<1024, 256>>>(input_signal);
    rnn_main<<<NCTA, THREADS, SMEM_BYTES>>>(hidden, w_in_w, w_hh_w, w_hh_b,
                                            w_out_w, alpha, noise_raw, pt, out);
}

// round 12
// speedup vs baseline: 1.2248x; 1.2248x over previous
#include <cuda_runtime.h>
#include <cuda_bf16.h>
#include <cstdint>

#define Bn 128
#define Tn 256
#define NHID 1024
#define NIN 128
#define NOUT 64
#define KTOT 1152
#define NCTA 128
#define THREADS 512
#define JGN 32          // j-groups
#define JSL 32          // j per CTA

// output layout: hidden_list [128][256][1024] ++ output_list [128][256][64] ++ h_final [128][1024]
#define OUT_HID 0
#define OUT_OUT 33554432
#define OUT_HF  35651584

// -------- device scratch --------
__device__ float g_act[2][NHID * Bn];              // tanh(h) [k][b], double buffered
__device__ float g_xT[Tn * NIN * Bn];              // x transposed [t][i][b]
__device__ float g_outpart[3][JGN * Bn * NOUT];    // out partials [jg][b*64+o], %3 (write t, read t+2)
__device__ unsigned g_arrive4[128];                // per-bg barrier counters (stride 32)
__device__ unsigned g_release4[128];

typedef unsigned long long ull;

__device__ __forceinline__ ull pack2(float x) {
    ull r; asm("mov.b64 %0, {%1, %1};" : "=l"(r) : "f"(x)); return r;
}
__device__ __forceinline__ void fma2(ull& c, ull a, ull b) {
    asm("fma.rn.f32x2 %0, %1, %2, %0;" : "+l"(c) : "l"(a), "l"(b));
}
__device__ __forceinline__ float2 unpack2(ull v) {
    float2 f; asm("mov.b64 {%0, %1}, %2;" : "=f"(f.x), "=f"(f.y) : "l"(v)); return f;
}
__device__ __forceinline__ void cpasync16(uint32_t dst, const float* src) {
    asm volatile("cp.async.cg.shared.global [%0], [%1], 16;" :: "r"(dst), "l"(src));
}
__device__ __forceinline__ void cpcommit() { asm volatile("cp.async.commit_group;"); }
template<int N> __device__ __forceinline__ void cpwait() {
    asm volatile("cp.async.wait_group %0;" :: "n"(N));
}

// fast exact-formula tanh: 1 - 2/(exp(2x)+1) via MUFU
__device__ __forceinline__ float fast_tanh(float x) {
    float e;
    asm("ex2.approx.f32 %0, %1;" : "=f"(e) : "f"(x * 2.8853900817779268f));
    float r;
    asm("rcp.approx.f32 %0, %1;" : "=f"(r) : "f"(e + 1.0f));
    return __fmaf_rn(-2.0f, r, 1.0f);
}

// -------- x transpose: g_xT[t][i][b] = input_signal[b][t][i] --------
__global__ void xT_kernel(const float* __restrict__ in) {
    __shared__ float s[128][33];
    int t = blockIdx.x >> 2, ig = blockIdx.x & 3;
    for (int idx = threadIdx.x; idx < 128 * 32; idx += 256) {
        int b = idx >> 5, ii = idx & 31;
        s[b][ii] = in[b * (Tn * NIN) + t * NIN + ig * 32 + ii];
    }
    __syncthreads();
    for (int idx = threadIdx.x; idx < 4096; idx += 256) {
        int ii = idx >> 7, b = idx & 127;
        g_xT[t * (NIN * Bn) + (ig * 32 + ii) * Bn + b] = s[b][ii];
    }
}

// -------- smem layout (float offsets) --------
#define SM_W    0                       // [1152][32] weights ([k][j])
#define SM_ACT  (SM_W + KTOT * 32)      // act_w[16][3][256] private rings (red aliases)
#define SM_WO   (SM_ACT + 16 * 768)     // [32][64] w_out slice
#define SM_HB   (SM_WO + 2048)          // h staged [b][j]  [32][36]
#define SM_TJ   (SM_HB + 32 * 36)       // tanh(h) [j][b]   [32][36]
#define SM_FLOATS (SM_TJ + 32 * 36)
#define SMEM_BYTES (SM_FLOATS * 4)

// barrier halves (monotonic counter, replay-safe); fence only in tid0 after syncthreads
#define GB_ARRIVE() do {                                                      \
        __syncthreads();                                                      \
        if (tid == 0) {                                                       \
            __threadfence();                                                  \
            bar_t += 32u;                                                     \
            unsigned a_ = atomicAdd(&g_arrive4[bg * 32], 1u) + 1u;            \
            if (a_ == bar_t) { atomicExch(&g_release4[bg * 32], bar_t); }     \
        }                                                                     \
    } while (0)

#define GB_WAIT() do {                                                        \
        if (tid == 0) {                                                       \
            while ((int)(*((volatile unsigned*)&g_release4[bg * 32]) - bar_t) < 0) {} \
        }                                                                     \
        __syncthreads();                                                      \
    } while (0)

__global__ void __launch_bounds__(THREADS, 1)
rnn_main(const float* __restrict__ hidden,
         const float* __restrict__ w_in,
         const float* __restrict__ w_hh,
         const float* __restrict__ w_b,
         const float* __restrict__ w_out,
         const float* __restrict__ alpha,
         const float* __restrict__ noise,
         const int* __restrict__ ptp,
         float* __restrict__ out)
{
    extern __shared__ float sm[];
    float* w_s   = sm + SM_W;
    float* act_s = sm + SM_ACT;
    float* red   = act_s;                 // alias: [8][32][36] = 9216 <= 12288 floats
    float* wo_s  = sm + SM_WO;
    float* hb    = sm + SM_HB;
    float* tj    = sm + SM_TJ;

    const int tid = threadIdx.x;
    const int cta = blockIdx.x;
    const int jg = cta & 31, bg = cta >> 5;
    const int jbase = jg * JSL, bbase = bg * 32;

    const int w   = tid >> 5;       // warp 0..15 : owns rows w*8..w*8+7 per chunk
    const int lid = tid & 31;
    const int bq  = lid & 7;
    const int jq  = lid >> 3;
    const int b0  = bq * 4;
    const int j0  = jq * 8;

    // ---- weights into smem [k][32j] (once) ----
    {
        int jj = tid >> 4;
        int kk = tid & 15;
        const float* wr = w_hh + (size_t)(jbase + jj) * NHID;
        for (int k = kk; k < NHID; k += 16)
            w_s[k * 32 + jj] = wr[k];
        const float* wi = w_in + (size_t)(jbase + jj) * NIN;
        for (int i = kk; i < NIN; i += 16)
            w_s[(NHID + i) * 32 + jj] = wi[i];
    }
    for (int idx = tid; idx < JSL * 64; idx += THREADS) {
        int jj = idx >> 6, o = idx & 63;
        wo_s[jj * 64 + o] = w_out[o * NHID + jbase + jj];
    }

    // ---- per-thread h ownership: bloc = tid>>4, j = jp, jp+1 ----
    const int bloc = tid >> 4;
    const int jp = (tid & 15) * 2;
    const int bown = bbase + bloc;

    float2 al2 = *(const float2*)&alpha[jbase + jp];
    float2 bi2 = *(const float2*)&w_b[jbase + jp];
    float2 ns2 = make_float2(0.05f * sqrtf(al2.x), 0.05f * sqrtf(al2.y));
    const int pt = *ptp;

    float2 hv = *(const float2*)&hidden[(size_t)bown * NHID + jbase + jp];
    float h0 = hv.x, h1 = hv.y;

    g_act[0][(jbase + jp) * Bn + bown]     = fast_tanh(h0);
    g_act[0][(jbase + jp + 1) * Bn + bown] = fast_tanh(h1);

    unsigned bar_t = 0;
    if (tid == 0) bar_t = *((volatile unsigned*)&g_release4[bg * 32]);

    // warp-private act ring: act_w[w][3][256]
    const uint32_t actw_u = (uint32_t)__cvta_generic_to_shared(act_s) + (uint32_t)(w * 768 * 4);
    const float* actw = act_s + w * 768;
    const int srow = lid >> 2;
    const int scol = (lid & 3) * 8;

#define WSTAGE(BASE, SLOT) do {                                               \
        const float* _s = (BASE) + (w * 8 + srow) * Bn + bbase + scol;        \
        uint32_t _d = actw_u + (uint32_t)(((SLOT) * 256 + srow * 32 + scol) * 4); \
        cpasync16(_d,      _s);                                               \
        cpasync16(_d + 16, _s + 4);                                           \
        cpcommit();                                                           \
    } while (0)

    // pre-stage item0 of step 0 (x chunk) into slot 0 — x needs no barrier
    WSTAGE(g_xT, 0);

    GB_ARRIVE();   // g_act[0] visible after release
    GB_WAIT();

    for (int t = 0; t < Tn; t++) {
        const float* asrc = g_act[t & 1];

        // stage item1 (= act chunk 0) into slot 1
        WSTAGE(asrc, 1);

        // ---- reduce out(t-2) partials: spread over 16 warps x 4 lanes ----
        if (t >= 2 && lid < 4) {
            int e = cta * 64 + w * 4 + lid;
            const float* src = g_outpart[(t - 2) % 3];
            float s = 0.f;
            #pragma unroll
            for (int r = 0; r < JGN; r++) s += __ldcg(src + r * (Bn * NOUT) + e);
            out[OUT_OUT + cta * (Tn * NOUT) + (t - 2) * NOUT + (w * 4 + lid)] = s;
        }

        ull acc[4][4];
        #pragma unroll
        for (int i = 0; i < 4; i++)
            #pragma unroll
            for (int j = 0; j < 4; j++) acc[i][j] = 0;

        // ---- GEMM: item order [x-chunk(8), act chunks 0..7]; warps free-run ----
        #pragma unroll 1
        for (int n = 0; n < 9; n++) {
            if (n <= 6) {
                WSTAGE(asrc + (n + 1) * 128 * Bn, (n + 2) % 3);
                cpwait<2>();
            } else if (n == 7) {
                cpwait<1>();
            } else {
                cpwait<0>();
            }
            __syncwarp();

            const int kc = (n == 0) ? 8 : (n - 1);
            const float* abk = actw + (n % 3) * 256 + b0;
            const float* wbk = w_s + (kc * 128 + w * 8) * 32 + j0;
            #pragma unroll
            for (int i = 0; i < 8; i++) {
                float4 av = *(const float4*)(abk + i * 32);
                ulonglong2 w01 = *(const ulonglong2*)(wbk + i * 32);
                ulonglong2 w23 = *(const ulonglong2*)(wbk + i * 32 + 4);
                ull a0 = pack2(av.x), a1 = pack2(av.y);
                ull a2 = pack2(av.z), a3 = pack2(av.w);
                fma2(acc[0][0], a0, w01.x); fma2(acc[0][1], a0, w01.y);
                fma2(acc[0][2], a0, w23.x); fma2(acc[0][3], a0, w23.y);
                fma2(acc[1][0], a1, w01.x); fma2(acc[1][1], a1, w01.y);
                fma2(acc[1][2], a1, w23.x); fma2(acc[1][3], a1, w23.y);
                fma2(acc[2][0], a2, w01.x); fma2(acc[2][1], a2, w01.y);
                fma2(acc[2][2], a2, w23.x); fma2(acc[2][3], a2, w23.y);
                fma2(acc[3][0], a3, w01.x); fma2(acc[3][1], a3, w01.y);
                fma2(acc[3][2], a3, w23.x); fma2(acc[3][3], a3, w23.y);
            }
        }
        __syncthreads();   // all warps done with act rings (red aliases them)

        // ---- 16-way k-split reduce: pair (w, w+8) via named barrier ----
        if (w >= 8) {
            float* rd = red + (w - 8) * (32 * 36);
            #pragma unroll
            for (int bb = 0; bb < 4; bb++) {
                float2 v0 = unpack2(acc[bb][0]);
                float2 v1 = unpack2(acc[bb][1]);
                float2 v2 = unpack2(acc[bb][2]);
                float2 v3 = unpack2(acc[bb][3]);
                *(float4*)(rd + (b0 + bb) * 36 + j0)     = make_float4(v0.x, v0.y, v1.x, v1.y);
                *(float4*)(rd + (b0 + bb) * 36 + j0 + 4) = make_float4(v2.x, v2.y, v3.x, v3.y);
            }
        }
        asm volatile("bar.sync %0, %1;" :: "r"((w & 7) + 1), "r"(64) : "memory");
        if (w < 8) {
            float* rd = red + w * (32 * 36);
            #pragma unroll
            for (int bb = 0; bb < 4; bb++) {
                float4 p0 = *(const float4*)(rd + (b0 + bb) * 36 + j0);
                float4 p1 = *(const float4*)(rd + (b0 + bb) * 36 + j0 + 4);
                float2 v0 = unpack2(acc[bb][0]);
                float2 v1 = unpack2(acc[bb][1]);
                float2 v2 = unpack2(acc[bb][2]);
                float2 v3 = unpack2(acc[bb][3]);
                *(float4*)(rd + (b0 + bb) * 36 + j0) =
                    make_float4(v0.x + p0.x, v0.y + p0.y, v1.x + p0.z, v1.y + p0.w);
                *(float4*)(rd + (b0 + bb) * 36 + j0 + 4) =
                    make_float4(v2.x + p1.x, v2.y + p1.y, v3.x + p1.z, v3.y + p1.w);
            }
        }
        __syncthreads();

        // ---- 8-way reduce + h update ----
        {
            float s0 = bi2.x, s1 = bi2.y;
            #pragma unroll
            for (int g = 0; g < 8; g++) {
                float2 v = *(const float2*)(red + g * (32 * 36) + bloc * 36 + jp);
                s0 += v.x; s1 += v.y;
            }
            h0 = (1.f - al2.x) * h0 + al2.x * s0;
            h1 = (1.f - al2.y) * h1 + al2.y * s1;
            if (t == pt) {
                float2 n = *(const float2*)&noise[(size_t)bown * NHID + jbase + jp];
                h0 += n.x * ns2.x;
                h1 += n.y * ns2.y;
            }
        }

        // stage hb [b][j], tj [j][b]
        *(float2*)&hb[bloc * 36 + jp] = make_float2(h0, h1);
        tj[(jp)     * 36 + bloc] = fast_tanh(h0);
        tj[(jp + 1) * 36 + bloc] = fast_tanh(h1);
        __syncthreads();     // red reads done -> ring slot 0 reusable; tj/hb ready

        // next act buffer write (512 threads, float2; row = local j) — MUST precede arrive
        {
            int rw = tid >> 4, q = (tid & 15) * 2;
            float2 a = *(const float2*)(tj + rw * 36 + q);
            *(float2*)&g_act[(t + 1) & 1][(jbase + rw) * Bn + bbase + q] = a;
        }

        // pre-stage next step's x chunk into ring slot 0 (no barrier needed)
        if (t + 1 < Tn)
            WSTAGE(g_xT + (t + 1) * (NIN * Bn), 0);

        // ---- ARRIVE, then shadow work during barrier skew ----
        GB_ARRIVE();

        // hidden_list STG (+h_final) from hb: nothing reads these; safe in shadow
        {
            int rw = tid >> 4, q = (tid & 15) * 2;
            float2 v = *(const float2*)(hb + rw * 36 + q);
            *(float2*)&out[OUT_HID + (size_t)(bbase + rw) * (Tn * NHID)
                           + (size_t)t * NHID + jbase + q] = v;
            if (t == Tn - 1)
                *(float2*)&out[OUT_HF + (size_t)(bbase + rw) * NHID + jbase + q] = v;
        }
        // out partial GEMM -> g_outpart[t%3]: read only at t+2, fenced by next arrive
        {
            const int br = tid >> 4;
            const int o0 = (tid & 15) * 4;
            float oa0 = 0.f, oa1 = 0.f, oa2 = 0.f, oa3 = 0.f;
            #pragma unroll
            for (int j = 0; j < JSL; j++) {
                float a = hb[br * 36 + j];
                float4 w4 = *(const float4*)(wo_s + j * 64 + o0);
                oa0 += a * w4.x; oa1 += a * w4.y; oa2 += a * w4.z; oa3 += a * w4.w;
            }
            float* op = g_outpart[t % 3] + jg * (Bn * NOUT);
            *(float4*)&op[(bbase + br) * 64 + o0] = make_float4(oa0, oa1, oa2, oa3);
        }

        GB_WAIT();
    }

    // ---- drain ----
    // out(Tn-2): written in step Tn-2's shadow, fenced before arrive(Tn-1) -> visible now
    if (lid < 4) {
        int e = cta * 64 + w * 4 + lid;
        const float* src = g_outpart[(Tn - 2) % 3];
        float s = 0.f;
        #pragma unroll
        for (int r = 0; r < JGN; r++) s += __ldcg(src + r * (Bn * NOUT) + e);
        out[OUT_OUT + cta * (Tn * NOUT) + (Tn - 2) * NOUT + (w * 4 + lid)] = s;
    }
    // extra barrier to publish outpart(Tn-1) (written after last arrive)
    GB_ARRIVE();
    GB_WAIT();
    if (lid < 4) {
        int e = cta * 64 + w * 4 + lid;
        const float* src = g_outpart[(Tn - 1) % 3];
        float s = 0.f;
        #pragma unroll
        for (int r = 0; r < JGN; r++) s += __ldcg(src + r * (Bn * NOUT) + e);
        out[OUT_OUT + cta * (Tn * NOUT) + (Tn - 1) * NOUT + (w * 4 + lid)] = s;
    }
#undef WSTAGE
}
#undef GB_ARRIVE
#undef GB_WAIT

// -------- launcher --------
extern "C" void kernel_launch(void* const* d_in, const int* in_sizes, int n_in,
                              void* d_out, int out_size)
{
    const float* input_signal = (const float*)d_in[0];
    const float* hidden       = (const float*)d_in[1];
    const float* w_in_w       = (const float*)d_in[2];
    const float* w_hh_w       = (const float*)d_in[3];
    const float* w_hh_b       = (const float*)d_in[4];
    const float* w_out_w      = (const float*)d_in[5];
    const float* alpha        = (const float*)d_in[6];
    const float* noise_raw    = (const float*)d_in[7];
    const int*   pt           = (const int*)d_in[8];
    float* out = (float*)d_out;

    cudaFuncSetAttribute(rnn_main, cudaFuncAttributeMaxDynamicSharedMemorySize, SMEM_BYTES);

    xT_kernel<<<1024, 256>>>(input_signal);
    rnn_main<<<NCTA, THREADS, SMEM_BYTES>>>(hidden, w_in_w, w_hh_w, w_hh_b,
                                            w_out_w, alpha, noise_raw, pt, out);
}

// round 13
// speedup vs baseline: 1.2263x; 1.0012x over previous
#include <cuda_runtime.h>
#include <cuda_bf16.h>
#include <cstdint>

#define Bn 128
#define Tn 256
#define NHID 1024
#define NIN 128
#define NOUT 64
#define KTOT 1152
#define NCTA 128
#define THREADS 512
#define JGN 32          // j-groups
#define JSL 32          // j per CTA

// output layout: hidden_list [128][256][1024] ++ output_list [128][256][64] ++ h_final [128][1024]
#define OUT_HID 0
#define OUT_OUT 33554432
#define OUT_HF  35651584

// -------- device scratch --------
__device__ float g_act[2][NHID * Bn];              // tanh(h) [k][b], double buffered
__device__ float g_xT[Tn * NIN * Bn];              // x transposed [t][i][b]
__device__ float g_outpart[3][JGN * Bn * NOUT];    // out partials [jg][b*64+o], %3 (write t, read t+2)
__device__ unsigned g_arrive4[128];                // per-bg barrier counters (stride 32)
__device__ unsigned g_release4[128];

typedef unsigned long long ull;

__device__ __forceinline__ ull pack2(float x) {
    ull r; asm("mov.b64 %0, {%1, %1};" : "=l"(r) : "f"(x)); return r;
}
__device__ __forceinline__ void fma2(ull& c, ull a, ull b) {
    asm("fma.rn.f32x2 %0, %1, %2, %0;" : "+l"(c) : "l"(a), "l"(b));
}
__device__ __forceinline__ float2 unpack2(ull v) {
    float2 f; asm("mov.b64 {%0, %1}, %2;" : "=f"(f.x), "=f"(f.y) : "l"(v)); return f;
}
__device__ __forceinline__ void cpasync16(uint32_t dst, const float* src) {
    asm volatile("cp.async.cg.shared.global [%0], [%1], 16;" :: "r"(dst), "l"(src));
}
__device__ __forceinline__ void cpcommit() { asm volatile("cp.async.commit_group;"); }
template<int N> __device__ __forceinline__ void cpwait() {
    asm volatile("cp.async.wait_group %0;" :: "n"(N));
}

// fast exact-formula tanh: 1 - 2/(exp(2x)+1) via MUFU
__device__ __forceinline__ float fast_tanh(float x) {
    float e;
    asm("ex2.approx.f32 %0, %1;" : "=f"(e) : "f"(x * 2.8853900817779268f));
    float r;
    asm("rcp.approx.f32 %0, %1;" : "=f"(r) : "f"(e + 1.0f));
    return __fmaf_rn(-2.0f, r, 1.0f);
}

// -------- x transpose: g_xT[t][i][b] = input_signal[b][t][i] --------
__global__ void xT_kernel(const float* __restrict__ in) {
    __shared__ float s[128][33];
    int t = blockIdx.x >> 2, ig = blockIdx.x & 3;
    for (int idx = threadIdx.x; idx < 128 * 32; idx += 256) {
        int b = idx >> 5, ii = idx & 31;
        s[b][ii] = in[b * (Tn * NIN) + t * NIN + ig * 32 + ii];
    }
    __syncthreads();
    for (int idx = threadIdx.x; idx < 4096; idx += 256) {
        int ii = idx >> 7, b = idx & 127;
        g_xT[t * (NIN * Bn) + (ig * 32 + ii) * Bn + b] = s[b][ii];
    }
}

// -------- smem layout (float offsets) --------
#define SM_W    0                       // [1152][32] weights ([k][j])
#define SM_ACT  (SM_W + KTOT * 32)      // act_w[16][3][256] private rings (red aliases)
#define SM_WO   (SM_ACT + 16 * 768)     // [32][64] w_out slice
#define SM_HB   (SM_WO + 2048)          // h staged [b][j]  [32][36]
#define SM_TJ   (SM_HB + 32 * 36)       // tanh(h) [j][b]   [32][36]
#define SM_FLOATS (SM_TJ + 32 * 36)
#define SMEM_BYTES (SM_FLOATS * 4)

// barrier halves (monotonic counter, replay-safe); fence only in tid0 after syncthreads
#define GB_ARRIVE() do {                                                      \
        __syncthreads();                                                      \
        if (tid == 0) {                                                       \
            __threadfence();                                                  \
            bar_t += 32u;                                                     \
            unsigned a_ = atomicAdd(&g_arrive4[bg * 32], 1u) + 1u;            \
            if (a_ == bar_t) { atomicExch(&g_release4[bg * 32], bar_t); }     \
        }                                                                     \
    } while (0)

#define GB_WAIT() do {                                                        \
        if (tid == 0) {                                                       \
            while ((int)(*((volatile unsigned*)&g_release4[bg * 32]) - bar_t) < 0) {} \
        }                                                                     \
        __syncthreads();                                                      \
    } while (0)

__global__ void __launch_bounds__(THREADS, 1)
rnn_main(const float* __restrict__ hidden,
         const float* __restrict__ w_in,
         const float* __restrict__ w_hh,
         const float* __restrict__ w_b,
         const float* __restrict__ w_out,
         const float* __restrict__ alpha,
         const float* __restrict__ noise,
         const int* __restrict__ ptp,
         float* __restrict__ out)
{
    extern __shared__ float sm[];
    float* w_s   = sm + SM_W;
    float* act_s = sm + SM_ACT;
    float* red   = act_s;                 // alias: [8][32][36] = 9216 <= 12288 floats
    float* wo_s  = sm + SM_WO;
    float* hb    = sm + SM_HB;
    float* tj    = sm + SM_TJ;

    const int tid = threadIdx.x;
    const int cta = blockIdx.x;
    const int jg = cta & 31, bg = cta >> 5;
    const int jbase = jg * JSL, bbase = bg * 32;

    const int w   = tid >> 5;       // warp 0..15 : owns rows w*8..w*8+7 per chunk
    const int lid = tid & 31;
    const int bq  = lid & 7;
    const int jq  = lid >> 3;
    const int b0  = bq * 4;
    const int j0  = jq * 8;

    // ---- weights into smem [k][32j] (once) ----
    {
        int jj = tid >> 4;
        int kk = tid & 15;
        const float* wr = w_hh + (size_t)(jbase + jj) * NHID;
        for (int k = kk; k < NHID; k += 16)
            w_s[k * 32 + jj] = wr[k];
        const float* wi = w_in + (size_t)(jbase + jj) * NIN;
        for (int i = kk; i < NIN; i += 16)
            w_s[(NHID + i) * 32 + jj] = wi[i];
    }
    for (int idx = tid; idx < JSL * 64; idx += THREADS) {
        int jj = idx >> 6, o = idx & 63;
        wo_s[jj * 64 + o] = w_out[o * NHID + jbase + jj];
    }

    // ---- per-thread h ownership: bloc = tid>>4, j = jp, jp+1 ----
    const int bloc = tid >> 4;
    const int jp = (tid & 15) * 2;
    const int bown = bbase + bloc;

    float2 al2 = *(const float2*)&alpha[jbase + jp];
    float2 bi2 = *(const float2*)&w_b[jbase + jp];
    float2 ns2 = make_float2(0.05f * sqrtf(al2.x), 0.05f * sqrtf(al2.y));
    const int pt = *ptp;

    float2 hv = *(const float2*)&hidden[(size_t)bown * NHID + jbase + jp];
    float h0 = hv.x, h1 = hv.y;

    g_act[0][(jbase + jp) * Bn + bown]     = fast_tanh(h0);
    g_act[0][(jbase + jp + 1) * Bn + bown] = fast_tanh(h1);

    unsigned bar_t = 0;
    if (tid == 0) bar_t = *((volatile unsigned*)&g_release4[bg * 32]);

    // warp-private act ring: act_w[w][3][256]
    const uint32_t actw_u = (uint32_t)__cvta_generic_to_shared(act_s) + (uint32_t)(w * 768 * 4);
    const float* actw = act_s + w * 768;
    const int srow = lid >> 2;
    const int scol = (lid & 3) * 8;

#define WSTAGE(BASE, SLOT) do {                                               \
        const float* _s = (BASE) + (w * 8 + srow) * Bn + bbase + scol;        \
        uint32_t _d = actw_u + (uint32_t)(((SLOT) * 256 + srow * 32 + scol) * 4); \
        cpasync16(_d,      _s);                                               \
        cpasync16(_d + 16, _s + 4);                                           \
        cpcommit();                                                           \
    } while (0)

    // pre-stage item0 of step 0 (x chunk) into slot 0 — x needs no barrier
    WSTAGE(g_xT, 0);

    GB_ARRIVE();   // g_act[0] visible after release
    GB_WAIT();

    for (int t = 0; t < Tn; t++) {
        const float* asrc = g_act[t & 1];

        // stage item1 (= act chunk 0) into slot 1
        WSTAGE(asrc, 1);

        // ---- reduce out(t-2) partials: spread over 16 warps x 4 lanes ----
        if (t >= 2 && lid < 4) {
            int e = cta * 64 + w * 4 + lid;
            const float* src = g_outpart[(t - 2) % 3];
            float s = 0.f;
            #pragma unroll
            for (int r = 0; r < JGN; r++) s += __ldcg(src + r * (Bn * NOUT) + e);
            out[OUT_OUT + cta * (Tn * NOUT) + (t - 2) * NOUT + (w * 4 + lid)] = s;
        }

        ull acc[4][4];
        #pragma unroll
        for (int i = 0; i < 4; i++)
            #pragma unroll
            for (int j = 0; j < 4; j++) acc[i][j] = 0;

        // ---- GEMM: item order [x-chunk(8), act chunks 0..7]; warps free-run ----
        #pragma unroll 1
        for (int n = 0; n < 9; n++) {
            if (n <= 6) {
                WSTAGE(asrc + (n + 1) * 128 * Bn, (n + 2) % 3);
                cpwait<2>();
            } else if (n == 7) {
                cpwait<1>();
            } else {
                cpwait<0>();
            }
            __syncwarp();

            const int kc = (n == 0) ? 8 : (n - 1);
            const float* abk = actw + (n % 3) * 256 + b0;
            const float* wbk = w_s + (kc * 128 + w * 8) * 32 + j0;
            #pragma unroll
            for (int i = 0; i < 8; i++) {
                float4 av = *(const float4*)(abk + i * 32);
                ulonglong2 w01 = *(const ulonglong2*)(wbk + i * 32);
                ulonglong2 w23 = *(const ulonglong2*)(wbk + i * 32 + 4);
                ull a0 = pack2(av.x), a1 = pack2(av.y);
                ull a2 = pack2(av.z), a3 = pack2(av.w);
                fma2(acc[0][0], a0, w01.x); fma2(acc[0][1], a0, w01.y);
                fma2(acc[0][2], a0, w23.x); fma2(acc[0][3], a0, w23.y);
                fma2(acc[1][0], a1, w01.x); fma2(acc[1][1], a1, w01.y);
                fma2(acc[1][2], a1, w23.x); fma2(acc[1][3], a1, w23.y);
                fma2(acc[2][0], a2, w01.x); fma2(acc[2][1], a2, w01.y);
                fma2(acc[2][2], a2, w23.x); fma2(acc[2][3], a2, w23.y);
                fma2(acc[3][0], a3, w01.x); fma2(acc[3][1], a3, w01.y);
                fma2(acc[3][2], a3, w23.x); fma2(acc[3][3], a3, w23.y);
            }
        }
        __syncthreads();   // all warps done with act rings (red aliases them)

        // ---- 16-way k-split reduce: pair (w, w+8) via named barrier ----
        if (w >= 8) {
            float* rd = red + (w - 8) * (32 * 36);
            #pragma unroll
            for (int bb = 0; bb < 4; bb++) {
                float2 v0 = unpack2(acc[bb][0]);
                float2 v1 = unpack2(acc[bb][1]);
                float2 v2 = unpack2(acc[bb][2]);
                float2 v3 = unpack2(acc[bb][3]);
                *(float4*)(rd + (b0 + bb) * 36 + j0)     = make_float4(v0.x, v0.y, v1.x, v1.y);
                *(float4*)(rd + (b0 + bb) * 36 + j0 + 4) = make_float4(v2.x, v2.y, v3.x, v3.y);
            }
        }
        asm volatile("bar.sync %0, %1;" :: "r"((w & 7) + 1), "r"(64) : "memory");
        if (w < 8) {
            float* rd = red + w * (32 * 36);
            #pragma unroll
            for (int bb = 0; bb < 4; bb++) {
                float4 p0 = *(const float4*)(rd + (b0 + bb) * 36 + j0);
                float4 p1 = *(const float4*)(rd + (b0 + bb) * 36 + j0 + 4);
                float2 v0 = unpack2(acc[bb][0]);
                float2 v1 = unpack2(acc[bb][1]);
                float2 v2 = unpack2(acc[bb][2]);
                float2 v3 = unpack2(acc[bb][3]);
                *(float4*)(rd + (b0 + bb) * 36 + j0) =
                    make_float4(v0.x + p0.x, v0.y + p0.y, v1.x + p0.z, v1.y + p0.w);
                *(float4*)(rd + (b0 + bb) * 36 + j0 + 4) =
                    make_float4(v2.x + p1.x, v2.y + p1.y, v3.x + p1.z, v3.y + p1.w);
            }
        }
        __syncthreads();

        // ---- 8-way reduce + h update ----
        {
            float s0 = bi2.x, s1 = bi2.y;
            #pragma unroll
            for (int g = 0; g < 8; g++) {
                float2 v = *(const float2*)(red + g * (32 * 36) + bloc * 36 + jp);
                s0 += v.x; s1 += v.y;
            }
            h0 = (1.f - al2.x) * h0 + al2.x * s0;
            h1 = (1.f - al2.y) * h1 + al2.y * s1;
            if (t == pt) {
                float2 n = *(const float2*)&noise[(size_t)bown * NHID + jbase + jp];
                h0 += n.x * ns2.x;
                h1 += n.y * ns2.y;
            }
        }

        // stage hb [b][j], tj [j][b]
        *(float2*)&hb[bloc * 36 + jp] = make_float2(h0, h1);
        tj[(jp)     * 36 + bloc] = fast_tanh(h0);
        tj[(jp + 1) * 36 + bloc] = fast_tanh(h1);
        __syncthreads();     // red reads done -> ring slot 0 reusable; tj/hb ready

        // next act buffer write (512 threads, float2; row = local j) — MUST precede arrive
        {
            int rw = tid >> 4, q = (tid & 15) * 2;
            float2 a = *(const float2*)(tj + rw * 36 + q);
            *(float2*)&g_act[(t + 1) & 1][(jbase + rw) * Bn + bbase + q] = a;
        }

        // pre-stage next step's x chunk into ring slot 0 (no barrier needed)
        if (t + 1 < Tn)
            WSTAGE(g_xT + (t + 1) * (NIN * Bn), 0);

        // ---- ARRIVE, then shadow work during barrier skew ----
        GB_ARRIVE();

        // hidden_list STG (+h_final) from hb: nothing reads these; safe in shadow
        {
            int rw = tid >> 4, q = (tid & 15) * 2;
            float2 v = *(const float2*)(hb + rw * 36 + q);
            *(float2*)&out[OUT_HID + (size_t)(bbase + rw) * (Tn * NHID)
                           + (size_t)t * NHID + jbase + q] = v;
            if (t == Tn - 1)
                *(float2*)&out[OUT_HF + (size_t)(bbase + rw) * NHID + jbase + q] = v;
        }
        // out partial GEMM -> g_outpart[t%3]: read only at t+2, fenced by next arrive
        {
            const int br = tid >> 4;
            const int o0 = (tid & 15) * 4;
            float oa0 = 0.f, oa1 = 0.f, oa2 = 0.f, oa3 = 0.f;
            #pragma unroll
            for (int j = 0; j < JSL; j++) {
                float a = hb[br * 36 + j];
                float4 w4 = *(const float4*)(wo_s + j * 64 + o0);
                oa0 += a * w4.x; oa1 += a * w4.y; oa2 += a * w4.z; oa3 += a * w4.w;
            }
            float* op = g_outpart[t % 3] + jg * (Bn * NOUT);
            *(float4*)&op[(bbase + br) * 64 + o0] = make_float4(oa0, oa1, oa2, oa3);
        }

        GB_WAIT();
    }

    // ---- drain ----
    // out(Tn-2): written in step Tn-2's shadow, fenced before arrive(Tn-1) -> visible now
    if (lid < 4) {
        int e = cta * 64 + w * 4 + lid;
        const float* src = g_outpart[(Tn - 2) % 3];
        float s = 0.f;
        #pragma unroll
        for (int r = 0; r < JGN; r++) s += __ldcg(src + r * (Bn * NOUT) + e);
        out[OUT_OUT + cta * (Tn * NOUT) + (Tn - 2) * NOUT + (w * 4 + lid)] = s;
    }
    // extra barrier to publish outpart(Tn-1) (written after last arrive)
    GB_ARRIVE();
    GB_WAIT();
    if (lid < 4) {
        int e = cta * 64 + w * 4 + lid;
        const float* src = g_outpart[(Tn - 1) % 3];
        float s = 0.f;
        #pragma unroll
        for (int r = 0; r < JGN; r++) s += __ldcg(src + r * (Bn * NOUT) + e);
        out[OUT_OUT + cta * (Tn * NOUT) + (Tn - 1) * NOUT + (w * 4 + lid)] = s;
    }
#undef WSTAGE
}
#undef GB_ARRIVE
#undef GB_WAIT

// -------- launcher --------
extern "C" void kernel_launch(void* const* d_in, const int* in_sizes, int n_in,
                              void* d_out, int out_size)
{
    const float* input_signal = (const float*)d_in[0];
    const float* hidden       = (const float*)d_in[1];
    const float* w_in_w       = (const float*)d_in[2];
    const float* w_hh_w       = (const float*)d_in[3];
    const float* w_hh_b       = (const float*)d_in[4];
    const float* w_out_w      = (const float*)d_in[5];
    const float* alpha        = (const float*)d_in[6];
    const float* noise_raw    = (const float*)d_in[7];
    const int*   pt           = (const int*)d_in[8];
    float* out = (float*)d_out;

    cudaFuncSetAttribute(rnn_main, cudaFuncAttributeMaxDynamicSharedMemorySize, SMEM_BYTES);

    xT_kernel<<<1024, 256>>>(input_signal);
    rnn_main<<<NCTA, THREADS, SMEM_BYTES>>>(hidden, w_in_w, w_hh_w, w_hh_b,
                                            w_out_w, alpha, noise_raw, pt, out);
}

// round 15
// speedup vs baseline: 1.3538x; 1.1040x over previous
#include <cuda_runtime.h>
#include <cuda_bf16.h>
#include <cstdint>

#define Bn 128
#define Tn 256
#define NHID 1024
#define NIN 128
#define NOUT 64
#define NCTA 128
#define THREADS 512
#define JGN 32
#define JSL 32

#define OUT_HID 0
#define OUT_OUT 33554432
#define OUT_HF  35651584

// -------- device scratch --------
__device__ __nv_bfloat16 g_abf[2][2][Bn * NHID];            // [par][plane][b*1024+k]
__device__ __nv_bfloat16 g_xbf[2][(size_t)Tn * Bn * NIN];   // [plane][(t*128+b)*128+i]
__device__ float g_outpart[3][JGN * Bn * NOUT];
__device__ unsigned g_arrive4[128];
__device__ unsigned g_release4[128];

__device__ __forceinline__ void cpa16(uint32_t d, const void* s) {
    asm volatile("cp.async.cg.shared.global [%0], [%1], 16;" :: "r"(d), "l"(s));
}
__device__ __forceinline__ void cpcommit() { asm volatile("cp.async.commit_group;"); }
template<int N> __device__ __forceinline__ void cpwait() {
    asm volatile("cp.async.wait_group %0;" :: "n"(N));
}
__device__ __forceinline__ float fast_tanh(float x) {
    float e; asm("ex2.approx.f32 %0, %1;" : "=f"(e) : "f"(x * 2.8853900817779268f));
    float r; asm("rcp.approx.f32 %0, %1;" : "=f"(r) : "f"(e + 1.0f));
    return __fmaf_rn(-2.0f, r, 1.0f);
}

#define LDM4(r, addr) \
    asm volatile("ldmatrix.sync.aligned.m8n8.x4.shared.b16 {%0,%1,%2,%3}, [%4];" \
        : "=r"((r)[0]), "=r"((r)[1]), "=r"((r)[2]), "=r"((r)[3]) : "r"(addr))

#define HMMA(d, a, b0, b1) \
    asm volatile("mma.sync.aligned.m16n8k16.row.col.f32.bf16.bf16.f32 " \
        "{%0,%1,%2,%3}, {%4,%5,%6,%7}, {%8,%9}, {%0,%1,%2,%3};" \
        : "+f"((d)[0]), "+f"((d)[1]), "+f"((d)[2]), "+f"((d)[3]) \
        : "r"((a)[0]), "r"((a)[1]), "r"((a)[2]), "r"((a)[3]), "r"(b0), "r"(b1))

// -------- x -> bf16 hi/lo planes, b-major per t: g_xbf[pl][(t*128+b)*128+i] --------
__global__ void xbf_kernel(const float* __restrict__ in) {
    int gid = blockIdx.x * 512 + threadIdx.x;     // 2048 blocks
    int i4 = gid & 31, t = (gid >> 5) & 255, b = gid >> 13;
    float4 v = *(const float4*)(in + ((size_t)b * 256 + t) * 128 + i4 * 4);
    float vv[4] = {v.x, v.y, v.z, v.w};
    unsigned short hi[4], lo[4];
    #pragma unroll
    for (int u = 0; u < 4; u++) {
        __nv_bfloat16 h = __float2bfloat16(vv[u]);
        __nv_bfloat16 l = __float2bfloat16(vv[u] - __bfloat162float(h));
        hi[u] = __bfloat16_as_ushort(h); lo[u] = __bfloat16_as_ushort(l);
    }
    size_t e = ((size_t)t * 128 + b) * 128 + i4 * 4;
    *(uint2*)&g_xbf[0][e] = make_uint2((uint32_t)hi[0] | ((uint32_t)hi[1] << 16),
                                       (uint32_t)hi[2] | ((uint32_t)hi[3] << 16));
    *(uint2*)&g_xbf[1][e] = make_uint2((uint32_t)lo[0] | ((uint32_t)lo[1] << 16),
                                       (uint32_t)lo[2] | ((uint32_t)lo[3] << 16));
}

// -------- smem byte layout --------
#define SMB_W     0                    // weights bf16: [2 planes][32 j][1152 k] XOR-swizzled (147456)
#define WPLANE    73728
#define SMB_RING  147456               // [16 warps][3 slots][2 planes][16 rows][16 bf16] (49152)
#define SMB_WO    196608               // [32 j][64 o] fp32 (8192)
#define SMB_HB    204800               // [32 b][34] fp32 (4352)
#define SMEM_BYTES 209152

#define GB_ARRIVE() do { __syncthreads(); if (tid == 0) { __threadfence(); bar_t += 32u; \
        unsigned a_ = atomicAdd(&g_arrive4[bg * 32], 1u) + 1u; \
        if (a_ == bar_t) atomicExch(&g_release4[bg * 32], bar_t); } } while (0)
#define GB_WAIT() do { if (tid == 0) { \
        while ((int)(*((volatile unsigned*)&g_release4[bg * 32]) - bar_t) < 0) {} } \
        __syncthreads(); } while (0)

__global__ void __launch_bounds__(THREADS, 1)
rnn_main(const float* __restrict__ hidden, const float* __restrict__ w_in,
         const float* __restrict__ w_hh, const float* __restrict__ w_b,
         const float* __restrict__ w_out, const float* __restrict__ alpha,
         const float* __restrict__ noise, const int* __restrict__ ptp,
         float* __restrict__ out)
{
    extern __shared__ char sm[];
    const int tid = threadIdx.x, cta = blockIdx.x;
    const int jg = cta & 31, bg = cta >> 5;
    const int jbase = jg * JSL, bbase = bg * 32;
    const uint32_t smu = (uint32_t)__cvta_generic_to_shared(sm);
    float* wo_s = (float*)(sm + SMB_WO);
    float* hb   = (float*)(sm + SMB_HB);
    float* red  = (float*)(sm + SMB_RING);   // alias rings: [8 kq][32 b][34] fp32 = 34816 <= 49152

    const int w = tid >> 5, lane = tid & 31;
    const int kq = w & 7, mh = w >> 3;

    // ---- weights -> smem bf16 hi/lo, [j][1152] with 16B-granule XOR swizzle ----
    {
        int jj = tid & 31, k0 = (tid >> 5) * 72;
        for (int i = 0; i < 72; i += 4) {
            int k = k0 + i;
            float4 v = (k < NHID)
                ? *(const float4*)(w_hh + (size_t)(jbase + jj) * NHID + k)
                : *(const float4*)(w_in + (size_t)(jbase + jj) * NIN + (k - NHID));
            float vv[4] = {v.x, v.y, v.z, v.w};
            #pragma unroll
            for (int u = 0; u < 4; u++) {
                __nv_bfloat16 h = __float2bfloat16(vv[u]);
                __nv_bfloat16 l = __float2bfloat16(vv[u] - __bfloat162float(h));
                int kk = k + u, gran = kk >> 3;
                int off = jj * 2304 + ((gran ^ (jj & 7)) << 4) + (kk & 7) * 2;
                *(__nv_bfloat16*)(sm + SMB_W + off) = h;
                *(__nv_bfloat16*)(sm + SMB_W + WPLANE + off) = l;
            }
        }
    }
    for (int idx = tid; idx < 2048; idx += THREADS) {
        int j = idx >> 6, o = idx & 63;
        wo_s[j * 64 + o] = w_out[(size_t)o * NHID + jbase + j];
    }

    // ---- per-thread h ownership (same as R12): bloc=tid>>4, jp=(tid&15)*2 ----
    const int bloc = tid >> 4, jp = (tid & 15) * 2;
    const int bown = bbase + bloc;
    float2 al2 = *(const float2*)&alpha[jbase + jp];
    float2 bi2 = *(const float2*)&w_b[jbase + jp];
    float2 ns2 = make_float2(0.05f * sqrtf(al2.x), 0.05f * sqrtf(al2.y));
    const int pt = *ptp;
    float2 hv = *(const float2*)&hidden[(size_t)bown * NHID + jbase + jp];
    float h0 = hv.x, h1 = hv.y;
    {
        float a0 = fast_tanh(h0), a1 = fast_tanh(h1);
        __nv_bfloat16 h0b = __float2bfloat16(a0), h1b = __float2bfloat16(a1);
        __nv_bfloat16 l0b = __float2bfloat16(a0 - __bfloat162float(h0b));
        __nv_bfloat16 l1b = __float2bfloat16(a1 - __bfloat162float(h1b));
        size_t e = (size_t)bown * NHID + jbase + jp;
        *(uint32_t*)&g_abf[0][0][e] = (uint32_t)__bfloat16_as_ushort(h0b) | ((uint32_t)__bfloat16_as_ushort(h1b) << 16);
        *(uint32_t*)&g_abf[0][1][e] = (uint32_t)__bfloat16_as_ushort(l0b) | ((uint32_t)__bfloat16_as_ushort(l1b) << 16);
    }

    unsigned bar_t = 0;
    if (tid == 0) bar_t = *((volatile unsigned*)&g_release4[bg * 32]);

    // ---- per-warp A ring + lane constants ----
    const uint32_t ring_u = smu + SMB_RING + (uint32_t)(w * 3072);
    const int spl = lane >> 4, srow = lane & 15;     // staging: plane, row
    const int rb = bbase + mh * 16 + srow;           // global b row this lane stages
    const uint32_t sd0 = (uint32_t)(spl * 512 + srow * 32 + (((0) ^ ((srow >> 2) & 1)) << 4));
    const uint32_t sd1 = (uint32_t)(spl * 512 + srow * 32 + (((1) ^ ((srow >> 2) & 1)) << 4));
    // ldmatrix A lane offset (row = lane&15, logical gran = lane>>4)
    const uint32_t a_off = (uint32_t)((lane & 15) * 32 + (((lane >> 4) ^ (((lane & 15) >> 2) & 1)) << 4));
    // B lane constants
    const int jb = ((lane >> 4) << 3) + (lane & 7);
    const int gplus = (lane >> 3) & 1;
    const uint32_t whi_u = smu + SMB_W, wlo_u = whi_u + WPLANE;

#define WSTAGE_ACT(PAR, C, SLOT) do { \
        const __nv_bfloat16* _s = g_abf[PAR][spl] + (size_t)rb * NHID + (C) * 128 + kq * 16; \
        uint32_t _d = ring_u + (uint32_t)((SLOT) * 1024); \
        cpa16(_d + sd0, _s); cpa16(_d + sd1, _s + 8); cpcommit(); } while (0)
#define WSTAGE_X(T, SLOT) do { \
        const __nv_bfloat16* _s = g_xbf[spl] + ((size_t)(T) * 128 + rb) * NIN + kq * 16; \
        uint32_t _d = ring_u + (uint32_t)((SLOT) * 1024); \
        cpa16(_d + sd0, _s); cpa16(_d + sd1, _s + 8); cpcommit(); } while (0)

    WSTAGE_X(0, 0);
    GB_ARRIVE(); GB_WAIT();

    for (int t = 0; t < Tn; t++) {
        const int par = t & 1;
        WSTAGE_ACT(par, 0, 1);

        // reduce out(t-2) partials (16 warps x 4 lanes)
        if (t >= 2 && lane < 4) {
            int e = cta * 64 + w * 4 + lane;
            const float* src = g_outpart[(t - 2) % 3];
            float s = 0.f;
            #pragma unroll
            for (int r = 0; r < JGN; r++) s += __ldcg(src + r * (Bn * NOUT) + e);
            out[OUT_OUT + (e >> 6) * (Tn * NOUT) + (t - 2) * NOUT + (e & 63)] = s;
        }

        float d[16];
        #pragma unroll
        for (int i = 0; i < 16; i++) d[i] = 0.f;

        #pragma unroll 1
        for (int n = 0; n < 9; n++) {
            if (n <= 6) { WSTAGE_ACT(par, n + 1, (n + 2) % 3); cpwait<2>(); }
            else if (n == 7) cpwait<1>();
            else cpwait<0>();
            __syncwarp();

            const int ckb = ((n == 0) ? 1024 : (n - 1) * 128) + kq * 16;
            const uint32_t ab = ring_u + (uint32_t)((n % 3) * 1024) + a_off;
            uint32_t ah[4], al[4], bh[8], bl[8];
            LDM4(ah, ab);
            LDM4(al, ab + 512);
            {
                int gx = ((ckb >> 3) + gplus) ^ (lane & 7);
                uint32_t b0a = (uint32_t)(jb * 2304 + (gx << 4));
                LDM4(bh,     whi_u + b0a);
                LDM4(bh + 4, whi_u + b0a + 16 * 2304);
                LDM4(bl,     wlo_u + b0a);
                LDM4(bl + 4, wlo_u + b0a + 16 * 2304);
            }
            #pragma unroll
            for (int nt = 0; nt < 4; nt++) {
                HMMA(d + nt * 4, ah, bh[nt * 2], bh[nt * 2 + 1]);
                HMMA(d + nt * 4, ah, bl[nt * 2], bl[nt * 2 + 1]);
                HMMA(d + nt * 4, al, bh[nt * 2], bh[nt * 2 + 1]);
            }
        }
        __syncthreads();   // rings fully consumed (red aliases them)

        // ---- dump D partials to red[kq][b][34] ----
        {
            int babs = mh * 16 + (lane >> 2);
            #pragma unroll
            for (int nt = 0; nt < 4; nt++) {
                int j = nt * 8 + (lane & 3) * 2;
                *(float2*)&red[(kq * 32 + babs) * 34 + j]     = make_float2(d[nt*4+0], d[nt*4+1]);
                *(float2*)&red[(kq * 32 + babs + 8) * 34 + j] = make_float2(d[nt*4+2], d[nt*4+3]);
            }
        }
        __syncthreads();

        // ---- 8-way reduce + h update ----
        {
            float s0 = bi2.x, s1 = bi2.y;
            #pragma unroll
            for (int g = 0; g < 8; g++) {
                float2 v = *(const float2*)&red[(g * 32 + bloc) * 34 + jp];
                s0 += v.x; s1 += v.y;
            }
            h0 = (1.f - al2.x) * h0 + al2.x * s0;
            h1 = (1.f - al2.y) * h1 + al2.y * s1;
            if (t == pt) {
                float2 n = *(const float2*)&noise[(size_t)bown * NHID + jbase + jp];
                h0 += n.x * ns2.x; h1 += n.y * ns2.y;
            }
        }
        *(float2*)&hb[bloc * 34 + jp] = make_float2(h0, h1);
        {
            float a0 = fast_tanh(h0), a1 = fast_tanh(h1);
            __nv_bfloat16 h0b = __float2bfloat16(a0), h1b = __float2bfloat16(a1);
            __nv_bfloat16 l0b = __float2bfloat16(a0 - __bfloat162float(h0b));
            __nv_bfloat16 l1b = __float2bfloat16(a1 - __bfloat162float(h1b));
            size_t e = (size_t)bown * NHID + jbase + jp;
            *(uint32_t*)&g_abf[par ^ 1][0][e] = (uint32_t)__bfloat16_as_ushort(h0b) | ((uint32_t)__bfloat16_as_ushort(h1b) << 16);
            *(uint32_t*)&g_abf[par ^ 1][1][e] = (uint32_t)__bfloat16_as_ushort(l0b) | ((uint32_t)__bfloat16_as_ushort(l1b) << 16);
        }
        __syncthreads();   // red reads done -> rings reusable; hb ready

        if (t + 1 < Tn) WSTAGE_X(t + 1, 0);

        GB_ARRIVE();

        // shadow: hidden_list (+h_final) from regs
        {
            float2 v = make_float2(h0, h1);
            *(float2*)&out[OUT_HID + (size_t)bown * (Tn * NHID) + (size_t)t * NHID + jbase + jp] = v;
            if (t == Tn - 1)
                *(float2*)&out[OUT_HF + (size_t)bown * NHID + jbase + jp] = v;
        }
        // shadow: out partial GEMM
        {
            const int br = tid >> 4, o0 = (tid & 15) * 4;
            float oa0 = 0.f, oa1 = 0.f, oa2 = 0.f, oa3 = 0.f;
            #pragma unroll
            for (int j = 0; j < JSL; j++) {
                float a = hb[br * 34 + j];
                float4 w4 = *(const float4*)(wo_s + j * 64 + o0);
                oa0 += a * w4.x; oa1 += a * w4.y; oa2 += a * w4.z; oa3 += a * w4.w;
            }
            float* op = g_outpart[t % 3] + jg * (Bn * NOUT);
            *(float4*)&op[(bbase + br) * 64 + o0] = make_float4(oa0, oa1, oa2, oa3);
        }

        GB_WAIT();
    }

    // ---- drain ----
    if (lane < 4) {
        int e = cta * 64 + w * 4 + lane;
        const float* src = g_outpart[(Tn - 2) % 3];
        float s = 0.f;
        #pragma unroll
        for (int r = 0; r < JGN; r++) s += __ldcg(src + r * (Bn * NOUT) + e);
        out[OUT_OUT + (e >> 6) * (Tn * NOUT) + (Tn - 2) * NOUT + (e & 63)] = s;
    }
    GB_ARRIVE(); GB_WAIT();
    if (lane < 4) {
        int e = cta * 64 + w * 4 + lane;
        const float* src = g_outpart[(Tn - 1) % 3];
        float s = 0.f;
        #pragma unroll
        for (int r = 0; r < JGN; r++) s += __ldcg(src + r * (Bn * NOUT) + e);
        out[OUT_OUT + (e >> 6) * (Tn * NOUT) + (Tn - 1) * NOUT + (e & 63)] = s;
    }
#undef WSTAGE_ACT
#undef WSTAGE_X
}
#undef GB_ARRIVE
#undef GB_WAIT

extern "C" void kernel_launch(void* const* d_in, const int* in_sizes, int n_in,
                              void* d_out, int out_size)
{
    const float* input_signal = (const float*)d_in[0];
    const float* hidden       = (const float*)d_in[1];
    const float* w_in_w       = (const float*)d_in[2];
    const float* w_hh_w       = (const float*)d_in[3];
    const float* w_hh_b       = (const float*)d_in[4];
    const float* w_out_w      = (const float*)d_in[5];
    const float* alpha        = (const float*)d_in[6];
    const float* noise_raw    = (const float*)d_in[7];
    const int*   pt           = (const int*)d_in[8];
    float* out = (float*)d_out;

    cudaFuncSetAttribute(rnn_main, cudaFuncAttributeMaxDynamicSharedMemorySize, SMEM_BYTES);
    xbf_kernel<<<2048, 512>>>(input_signal);
    rnn_main<<<NCTA, THREADS, SMEM_BYTES>>>(hidden, w_in_w, w_hh_w, w_hh_b,
                                            w_out_w, alpha, noise_raw, pt, out);
}

// round 16
// speedup vs baseline: 1.4216x; 1.0500x over previous
#include <cuda_runtime.h>
#include <cuda_bf16.h>
#include <cstdint>

#define Bn 128
#define Tn 256
#define NHID 1024
#define NIN 128
#define NOUT 64
#define NCTA 128
#define THREADS 512
#define JGN 32
#define JSL 32

#define OUT_HID 0
#define OUT_OUT 33554432
#define OUT_HF  35651584

// -------- device scratch --------
__device__ __nv_bfloat16 g_abf[2][2][Bn * NHID];            // [par][plane][b*1024+k]
__device__ __nv_bfloat16 g_xbf[2][(size_t)Tn * Bn * NIN];   // [plane][(t*128+b)*128+i]
__device__ float g_outpart[3][JGN * Bn * NOUT];
__device__ unsigned g_arrive4[128];
__device__ unsigned g_release4[128];

__device__ __forceinline__ void cpa16(uint32_t d, const void* s) {
    asm volatile("cp.async.cg.shared.global [%0], [%1], 16;" :: "r"(d), "l"(s));
}
__device__ __forceinline__ void cpcommit() { asm volatile("cp.async.commit_group;"); }
template<int N> __device__ __forceinline__ void cpwait() {
    asm volatile("cp.async.wait_group %0;" :: "n"(N));
}
__device__ __forceinline__ float fast_tanh(float x) {
    float e; asm("ex2.approx.f32 %0, %1;" : "=f"(e) : "f"(x * 2.8853900817779268f));
    float r; asm("rcp.approx.f32 %0, %1;" : "=f"(r) : "f"(e + 1.0f));
    return __fmaf_rn(-2.0f, r, 1.0f);
}

#define LDM4(r, addr) \
    asm volatile("ldmatrix.sync.aligned.m8n8.x4.shared.b16 {%0,%1,%2,%3}, [%4];" \
        : "=r"((r)[0]), "=r"((r)[1]), "=r"((r)[2]), "=r"((r)[3]) : "r"(addr))

#define HMMA(d, a, b0, b1) \
    asm volatile("mma.sync.aligned.m16n8k16.row.col.f32.bf16.bf16.f32 " \
        "{%0,%1,%2,%3}, {%4,%5,%6,%7}, {%8,%9}, {%0,%1,%2,%3};" \
        : "+f"((d)[0]), "+f"((d)[1]), "+f"((d)[2]), "+f"((d)[3]) \
        : "r"((a)[0]), "r"((a)[1]), "r"((a)[2]), "r"((a)[3]), "r"(b0), "r"(b1))

// -------- x -> bf16 hi/lo planes, b-major per t --------
__global__ void xbf_kernel(const float* __restrict__ in) {
    int gid = blockIdx.x * 512 + threadIdx.x;
    int i4 = gid & 31, t = (gid >> 5) & 255, b = gid >> 13;
    float4 v = *(const float4*)(in + ((size_t)b * 256 + t) * 128 + i4 * 4);
    float vv[4] = {v.x, v.y, v.z, v.w};
    unsigned short hi[4], lo[4];
    #pragma unroll
    for (int u = 0; u < 4; u++) {
        __nv_bfloat16 h = __float2bfloat16(vv[u]);
        __nv_bfloat16 l = __float2bfloat16(vv[u] - __bfloat162float(h));
        hi[u] = __bfloat16_as_ushort(h); lo[u] = __bfloat16_as_ushort(l);
    }
    size_t e = ((size_t)t * 128 + b) * 128 + i4 * 4;
    *(uint2*)&g_xbf[0][e] = make_uint2((uint32_t)hi[0] | ((uint32_t)hi[1] << 16),
                                       (uint32_t)hi[2] | ((uint32_t)hi[3] << 16));
    *(uint2*)&g_xbf[1][e] = make_uint2((uint32_t)lo[0] | ((uint32_t)lo[1] << 16),
                                       (uint32_t)lo[2] | ((uint32_t)lo[3] << 16));
}

// -------- smem byte layout --------
#define SMB_W     0                    // weights bf16 hi/lo, [j][1152] XOR-swizzled (147456)
#define WPLANE    73728
#define SMB_RING  147456               // [16 warps][4 slots][1024B] (65536); red aliases
#define SMB_WO    212992               // [32 j][64 o] fp32 (8192)
#define SMB_HB    221184               // [32 b][34] fp32 (4352)
#define SMEM_BYTES 225536

#define GB_ARRIVE() do { __syncthreads(); if (tid == 0) { __threadfence(); bar_t += 32u; \
        unsigned a_ = atomicAdd(&g_arrive4[bg * 32], 1u) + 1u; \
        if (a_ == bar_t) atomicExch(&g_release4[bg * 32], bar_t); } } while (0)
#define GB_WAIT() do { if (tid == 0) { \
        while ((int)(*((volatile unsigned*)&g_release4[bg * 32]) - bar_t) < 0) {} } \
        __syncthreads(); } while (0)

__global__ void __launch_bounds__(THREADS, 1)
rnn_main(const float* __restrict__ hidden, const float* __restrict__ w_in,
         const float* __restrict__ w_hh, const float* __restrict__ w_b,
         const float* __restrict__ w_out, const float* __restrict__ alpha,
         const float* __restrict__ noise, const int* __restrict__ ptp,
         float* __restrict__ out)
{
    extern __shared__ char sm[];
    const int tid = threadIdx.x, cta = blockIdx.x;
    const int jg = cta & 31, bg = cta >> 5;
    const int jbase = jg * JSL, bbase = bg * 32;
    const uint32_t smu = (uint32_t)__cvta_generic_to_shared(sm);
    float* wo_s = (float*)(sm + SMB_WO);
    float* hb   = (float*)(sm + SMB_HB);
    float* red  = (float*)(sm + SMB_RING);   // alias rings: [8][32][34] fp32 = 34816 <= 65536

    const int w = tid >> 5, lane = tid & 31;
    const int kq = w & 7, mh = w >> 3;

    // ---- weights -> smem bf16 hi/lo, [j][1152] with 16B-granule XOR swizzle ----
    {
        int jj = tid & 31, k0 = (tid >> 5) * 72;
        for (int i = 0; i < 72; i += 4) {
            int k = k0 + i;
            float4 v = (k < NHID)
                ? *(const float4*)(w_hh + (size_t)(jbase + jj) * NHID + k)
                : *(const float4*)(w_in + (size_t)(jbase + jj) * NIN + (k - NHID));
            float vv[4] = {v.x, v.y, v.z, v.w};
            #pragma unroll
            for (int u = 0; u < 4; u++) {
                __nv_bfloat16 h = __float2bfloat16(vv[u]);
                __nv_bfloat16 l = __float2bfloat16(vv[u] - __bfloat162float(h));
                int kk = k + u, gran = kk >> 3;
                int off = jj * 2304 + ((gran ^ (jj & 7)) << 4) + (kk & 7) * 2;
                *(__nv_bfloat16*)(sm + SMB_W + off) = h;
                *(__nv_bfloat16*)(sm + SMB_W + WPLANE + off) = l;
            }
        }
    }
    for (int idx = tid; idx < 2048; idx += THREADS) {
        int j = idx >> 6, o = idx & 63;
        wo_s[j * 64 + o] = w_out[(size_t)o * NHID + jbase + j];
    }

    // ---- per-thread h ownership: bloc=tid>>4, jp=(tid&15)*2 ----
    const int bloc = tid >> 4, jp = (tid & 15) * 2;
    const int bown = bbase + bloc;
    float2 al2 = *(const float2*)&alpha[jbase + jp];
    float2 bi2 = *(const float2*)&w_b[jbase + jp];
    float2 ns2 = make_float2(0.05f * sqrtf(al2.x), 0.05f * sqrtf(al2.y));
    const int pt = *ptp;
    float2 hv = *(const float2*)&hidden[(size_t)bown * NHID + jbase + jp];
    float h0 = hv.x, h1 = hv.y;
    {
        float a0 = fast_tanh(h0), a1 = fast_tanh(h1);
        __nv_bfloat16 h0b = __float2bfloat16(a0), h1b = __float2bfloat16(a1);
        __nv_bfloat16 l0b = __float2bfloat16(a0 - __bfloat162float(h0b));
        __nv_bfloat16 l1b = __float2bfloat16(a1 - __bfloat162float(h1b));
        size_t e = (size_t)bown * NHID + jbase + jp;
        *(uint32_t*)&g_abf[0][0][e] = (uint32_t)__bfloat16_as_ushort(h0b) | ((uint32_t)__bfloat16_as_ushort(h1b) << 16);
        *(uint32_t*)&g_abf[0][1][e] = (uint32_t)__bfloat16_as_ushort(l0b) | ((uint32_t)__bfloat16_as_ushort(l1b) << 16);
    }

    unsigned bar_t = 0;
    if (tid == 0) bar_t = *((volatile unsigned*)&g_release4[bg * 32]);

    // ---- per-warp A ring (4 slots) + lane constants ----
    const uint32_t ring_u = smu + SMB_RING + (uint32_t)(w * 4096);
    const int spl = lane >> 4, srow = lane & 15;
    const int rb = bbase + mh * 16 + srow;
    const uint32_t sd0 = (uint32_t)(spl * 512 + srow * 32 + (((0) ^ ((srow >> 2) & 1)) << 4));
    const uint32_t sd1 = (uint32_t)(spl * 512 + srow * 32 + (((1) ^ ((srow >> 2) & 1)) << 4));
    const uint32_t a_off = (uint32_t)((lane & 15) * 32 + (((lane >> 4) ^ (((lane & 15) >> 2) & 1)) << 4));
    const int jb = ((lane >> 4) << 3) + (lane & 7);
    const int gplus = (lane >> 3) & 1;
    const uint32_t whi_u = smu + SMB_W, wlo_u = whi_u + WPLANE;

    // hoisted staging pointers (per-step act base updated in loop)
    const size_t arow = (size_t)rb * NHID + kq * 16;
    const __nv_bfloat16* xrowbase = g_xbf[spl] + (size_t)rb * NIN + kq * 16;

#define STG(SRC, SLOT) do { \
        uint32_t _d = ring_u + (uint32_t)((SLOT) * 1024); \
        cpa16(_d + sd0, (SRC)); cpa16(_d + sd1, (SRC) + 8); cpcommit(); } while (0)

    // pre-stage x(0) into slot 0
    STG(xrowbase, 0);
    GB_ARRIVE(); GB_WAIT();

    for (int t = 0; t < Tn; t++) {
        const int par = t & 1;
        const __nv_bfloat16* abase = g_abf[par][spl] + arow;

        // stage act chunks 0,1,2 into slots 1,2,3 (item n -> slot n&3)
        STG(abase, 1);
        STG(abase + 128, 2);
        STG(abase + 256, 3);

        float d[16];
        #pragma unroll
        for (int i = 0; i < 16; i++) d[i] = 0.f;

        #pragma unroll 1
        for (int n = 0; n < 9; n++) {
            if (n >= 1 && n <= 5) { STG(abase + (n + 2) * 128, (n - 1) & 3); cpwait<3>(); }
            else if (n == 0) cpwait<3>();
            else if (n == 6) cpwait<2>();
            else if (n == 7) cpwait<1>();
            else cpwait<0>();
            __syncwarp();

            const int ckb = ((n == 0) ? 1024 : (n - 1) * 128) + kq * 16;
            const uint32_t ab = ring_u + (uint32_t)((n & 3) * 1024) + a_off;
            uint32_t ah[4], al[4], bh[8], bl[8];
            LDM4(ah, ab);
            LDM4(al, ab + 512);
            {
                int gx = ((ckb >> 3) + gplus) ^ (lane & 7);
                uint32_t b0a = (uint32_t)(jb * 2304 + (gx << 4));
                LDM4(bh,     whi_u + b0a);
                LDM4(bh + 4, whi_u + b0a + 16 * 2304);
                LDM4(bl,     wlo_u + b0a);
                LDM4(bl + 4, wlo_u + b0a + 16 * 2304);
            }
            #pragma unroll
            for (int nt = 0; nt < 4; nt++) {
                HMMA(d + nt * 4, ah, bh[nt * 2], bh[nt * 2 + 1]);
                HMMA(d + nt * 4, ah, bl[nt * 2], bl[nt * 2 + 1]);
                HMMA(d + nt * 4, al, bh[nt * 2], bh[nt * 2 + 1]);
            }
        }
        __syncthreads();   // rings fully consumed (red aliases them)

        // ---- dump D partials to red[kq][b][34] ----
        {
            int babs = mh * 16 + (lane >> 2);
            #pragma unroll
            for (int nt = 0; nt < 4; nt++) {
                int j = nt * 8 + (lane & 3) * 2;
                *(float2*)&red[(kq * 32 + babs) * 34 + j]     = make_float2(d[nt*4+0], d[nt*4+1]);
                *(float2*)&red[(kq * 32 + babs + 8) * 34 + j] = make_float2(d[nt*4+2], d[nt*4+3]);
            }
        }
        __syncthreads();

        // ---- 8-way reduce + h update ----
        {
            float s0 = bi2.x, s1 = bi2.y;
            #pragma unroll
            for (int g = 0; g < 8; g++) {
                float2 v = *(const float2*)&red[(g * 32 + bloc) * 34 + jp];
                s0 += v.x; s1 += v.y;
            }
            h0 = (1.f - al2.x) * h0 + al2.x * s0;
            h1 = (1.f - al2.y) * h1 + al2.y * s1;
            if (t == pt) {
                float2 n = *(const float2*)&noise[(size_t)bown * NHID + jbase + jp];
                h0 += n.x * ns2.x; h1 += n.y * ns2.y;
            }
        }
        *(float2*)&hb[bloc * 34 + jp] = make_float2(h0, h1);
        {
            float a0 = fast_tanh(h0), a1 = fast_tanh(h1);
            __nv_bfloat16 h0b = __float2bfloat16(a0), h1b = __float2bfloat16(a1);
            __nv_bfloat16 l0b = __float2bfloat16(a0 - __bfloat162float(h0b));
            __nv_bfloat16 l1b = __float2bfloat16(a1 - __bfloat162float(h1b));
            size_t e = (size_t)bown * NHID + jbase + jp;
            *(uint32_t*)&g_abf[par ^ 1][0][e] = (uint32_t)__bfloat16_as_ushort(h0b) | ((uint32_t)__bfloat16_as_ushort(h1b) << 16);
            *(uint32_t*)&g_abf[par ^ 1][1][e] = (uint32_t)__bfloat16_as_ushort(l0b) | ((uint32_t)__bfloat16_as_ushort(l1b) << 16);
        }
        __syncthreads();   // red reads done -> rings reusable; hb ready

        if (t + 1 < Tn) STG(xrowbase + (size_t)(t + 1) * (128 * NIN), 0);

        GB_ARRIVE();

        // ======== shadow work during barrier skew ========
        // hidden_list (+h_final) from regs
        {
            float2 v = make_float2(h0, h1);
            *(float2*)&out[OUT_HID + (size_t)bown * (Tn * NHID) + (size_t)t * NHID + jbase + jp] = v;
            if (t == Tn - 1)
                *(float2*)&out[OUT_HF + (size_t)bown * NHID + jbase + jp] = v;
        }
        // out partial GEMM
        {
            const int br = tid >> 4, o0 = (tid & 15) * 4;
            float oa0 = 0.f, oa1 = 0.f, oa2 = 0.f, oa3 = 0.f;
            #pragma unroll
            for (int j = 0; j < JSL; j++) {
                float a = hb[br * 34 + j];
                float4 w4 = *(const float4*)(wo_s + j * 64 + o0);
                oa0 += a * w4.x; oa1 += a * w4.y; oa2 += a * w4.z; oa3 += a * w4.w;
            }
            float* op = g_outpart[t % 3] + jg * (Bn * NOUT);
            *(float4*)&op[(bbase + br) * 64 + o0] = make_float4(oa0, oa1, oa2, oa3);
        }
        // reduce out(t-2) partials (16 warps x 4 lanes) — fenced by arrive(t-1)
        if (t >= 2 && lane < 4) {
            int e = cta * 64 + w * 4 + lane;
            const float* src = g_outpart[(t - 2) % 3];
            float s = 0.f;
            #pragma unroll
            for (int r = 0; r < JGN; r++) s += __ldcg(src + r * (Bn * NOUT) + e);
            out[OUT_OUT + (e >> 6) * (Tn * NOUT) + (t - 2) * NOUT + (e & 63)] = s;
        }

        GB_WAIT();
    }

    // ---- drain ----
    if (lane < 4) {
        int e = cta * 64 + w * 4 + lane;
        const float* src = g_outpart[(Tn - 2) % 3];
        float s = 0.f;
        #pragma unroll
        for (int r = 0; r < JGN; r++) s += __ldcg(src + r * (Bn * NOUT) + e);
        out[OUT_OUT + (e >> 6) * (Tn * NOUT) + (Tn - 2) * NOUT + (e & 63)] = s;
    }
    GB_ARRIVE(); GB_WAIT();
    if (lane < 4) {
        int e = cta * 64 + w * 4 + lane;
        const float* src = g_outpart[(Tn - 1) % 3];
        float s = 0.f;
        #pragma unroll
        for (int r = 0; r < JGN; r++) s += __ldcg(src + r * (Bn * NOUT) + e);
        out[OUT_OUT + (e >> 6) * (Tn * NOUT) + (Tn - 1) * NOUT + (e & 63)] = s;
    }
#undef STG
}
#undef GB_ARRIVE
#undef GB_WAIT

extern "C" void kernel_launch(void* const* d_in, const int* in_sizes, int n_in,
                              void* d_out, int out_size)
{
    const float* input_signal = (const float*)d_in[0];
    const float* hidden       = (const float*)d_in[1];
    const float* w_in_w       = (const float*)d_in[2];
    const float* w_hh_w       = (const float*)d_in[3];
    const float* w_hh_b       = (const float*)d_in[4];
    const float* w_out_w      = (const float*)d_in[5];
    const float* alpha        = (const float*)d_in[6];
    const float* noise_raw    = (const float*)d_in[7];
    const int*   pt           = (const int*)d_in[8];
    float* out = (float*)d_out;

    cudaFuncSetAttribute(rnn_main, cudaFuncAttributeMaxDynamicSharedMemorySize, SMEM_BYTES);
    xbf_kernel<<<2048, 512>>>(input_signal);
    rnn_main<<<NCTA, THREADS, SMEM_BYTES>>>(hidden, w_in_w, w_hh_w, w_hh_b,
                                            w_out_w, alpha, noise_raw, pt, out);
}

// round 17
// speedup vs baseline: 1.4304x; 1.0062x over previous
#include <cuda_runtime.h>
#include <cuda_bf16.h>
#include <cstdint>

#define Bn 128
#define Tn 256
#define NHID 1024
#define NIN 128
#define NOUT 64
#define NCTA 128
#define THREADS 512
#define JGN 32
#define JSL 32

#define OUT_HID 0
#define OUT_OUT 33554432
#define OUT_HF  35651584

// -------- device scratch --------
__device__ __nv_bfloat16 g_abf[2][2][Bn * NHID];            // [par][plane][b*1024+k]
__device__ __nv_bfloat16 g_xbf[2][(size_t)Tn * Bn * NIN];   // [plane][(t*128+b)*128+i]
__device__ float g_outpart[3][JGN * Bn * NOUT];
__device__ unsigned g_arrive4[128];
__device__ unsigned g_release4[128];

__device__ __forceinline__ void cpa16(uint32_t d, const void* s) {
    asm volatile("cp.async.cg.shared.global [%0], [%1], 16;" :: "r"(d), "l"(s));
}
__device__ __forceinline__ void cpcommit() { asm volatile("cp.async.commit_group;"); }
template<int N> __device__ __forceinline__ void cpwait() {
    asm volatile("cp.async.wait_group %0;" :: "n"(N));
}
__device__ __forceinline__ float fast_tanh(float x) {
    float e; asm("ex2.approx.f32 %0, %1;" : "=f"(e) : "f"(x * 2.8853900817779268f));
    float r; asm("rcp.approx.f32 %0, %1;" : "=f"(r) : "f"(e + 1.0f));
    return __fmaf_rn(-2.0f, r, 1.0f);
}

#define LDM4(r, addr) \
    asm volatile("ldmatrix.sync.aligned.m8n8.x4.shared.b16 {%0,%1,%2,%3}, [%4];" \
        : "=r"((r)[0]), "=r"((r)[1]), "=r"((r)[2]), "=r"((r)[3]) : "r"(addr))

#define HMMA(d, a, b0, b1) \
    asm volatile("mma.sync.aligned.m16n8k16.row.col.f32.bf16.bf16.f32 " \
        "{%0,%1,%2,%3}, {%4,%5,%6,%7}, {%8,%9}, {%0,%1,%2,%3};" \
        : "+f"((d)[0]), "+f"((d)[1]), "+f"((d)[2]), "+f"((d)[3]) \
        : "r"((a)[0]), "r"((a)[1]), "r"((a)[2]), "r"((a)[3]), "r"(b0), "r"(b1))

// -------- x -> bf16 hi/lo planes, b-major per t --------
__global__ void xbf_kernel(const float* __restrict__ in) {
    int gid = blockIdx.x * 512 + threadIdx.x;
    int i4 = gid & 31, t = (gid >> 5) & 255, b = gid >> 13;
    float4 v = *(const float4*)(in + ((size_t)b * 256 + t) * 128 + i4 * 4);
    float vv[4] = {v.x, v.y, v.z, v.w};
    unsigned short hi[4], lo[4];
    #pragma unroll
    for (int u = 0; u < 4; u++) {
        __nv_bfloat16 h = __float2bfloat16(vv[u]);
        __nv_bfloat16 l = __float2bfloat16(vv[u] - __bfloat162float(h));
        hi[u] = __bfloat16_as_ushort(h); lo[u] = __bfloat16_as_ushort(l);
    }
    size_t e = ((size_t)t * 128 + b) * 128 + i4 * 4;
    *(uint2*)&g_xbf[0][e] = make_uint2((uint32_t)hi[0] | ((uint32_t)hi[1] << 16),
                                       (uint32_t)hi[2] | ((uint32_t)hi[3] << 16));
    *(uint2*)&g_xbf[1][e] = make_uint2((uint32_t)lo[0] | ((uint32_t)lo[1] << 16),
                                       (uint32_t)lo[2] | ((uint32_t)lo[3] << 16));
}

// -------- smem byte layout --------
#define SMB_W     0                    // weights bf16 hi/lo, [j][1152] XOR-swizzled (147456)
#define WPLANE    73728
#define SMB_RING  147456               // [16 warps][4 slots][1024B] (65536); red aliases
#define SMB_WO    212992               // [32 j][64 o] fp32 (8192)
#define SMB_HB    221184               // [32 b][34] fp32 (4352)
#define SMEM_BYTES 225536

// arrive: block sync + tid0 fence/atomic; all threads track bar_t
#define GB_ARRIVE() do { __syncthreads(); bar_t += 32u; \
        if (tid == 0) { __threadfence(); \
            unsigned a_ = atomicAdd(&g_arrive4[bg * 32], 1u) + 1u; \
            if (a_ == bar_t) atomicExch(&g_release4[bg * 32], bar_t); } } while (0)
// wait: per-warp (lane0 polls, warp-local sync) — warps decouple at step start
#define GB_WAIT() do { if (lane == 0) { \
        while ((int)(*((volatile unsigned*)&g_release4[bg * 32]) - bar_t) < 0) {} } \
        __syncwarp(); } while (0)

__global__ void __launch_bounds__(THREADS, 1)
rnn_main(const float* __restrict__ hidden, const float* __restrict__ w_in,
         const float* __restrict__ w_hh, const float* __restrict__ w_b,
         const float* __restrict__ w_out, const float* __restrict__ alpha,
         const float* __restrict__ noise, const int* __restrict__ ptp,
         float* __restrict__ out)
{
    extern __shared__ char sm[];
    const int tid = threadIdx.x, cta = blockIdx.x;
    const int jg = cta & 31, bg = cta >> 5;
    const int jbase = jg * JSL, bbase = bg * 32;
    const uint32_t smu = (uint32_t)__cvta_generic_to_shared(sm);
    float* wo_s = (float*)(sm + SMB_WO);
    float* hb   = (float*)(sm + SMB_HB);
    float* red  = (float*)(sm + SMB_RING);   // alias rings: [8][32][34] fp32 = 34816 <= 65536

    const int w = tid >> 5, lane = tid & 31;
    const int kq = w & 7, mh = w >> 3;

    // ---- weights -> smem bf16 hi/lo, [j][1152] with 16B-granule XOR swizzle ----
    {
        int jj = tid & 31, k0 = (tid >> 5) * 72;
        for (int i = 0; i < 72; i += 4) {
            int k = k0 + i;
            float4 v = (k < NHID)
                ? *(const float4*)(w_hh + (size_t)(jbase + jj) * NHID + k)
                : *(const float4*)(w_in + (size_t)(jbase + jj) * NIN + (k - NHID));
            float vv[4] = {v.x, v.y, v.z, v.w};
            #pragma unroll
            for (int u = 0; u < 4; u++) {
                __nv_bfloat16 h = __float2bfloat16(vv[u]);
                __nv_bfloat16 l = __float2bfloat16(vv[u] - __bfloat162float(h));
                int kk = k + u, gran = kk >> 3;
                int off = jj * 2304 + ((gran ^ (jj & 7)) << 4) + (kk & 7) * 2;
                *(__nv_bfloat16*)(sm + SMB_W + off) = h;
                *(__nv_bfloat16*)(sm + SMB_W + WPLANE + off) = l;
            }
        }
    }
    for (int idx = tid; idx < 2048; idx += THREADS) {
        int j = idx >> 6, o = idx & 63;
        wo_s[j * 64 + o] = w_out[(size_t)o * NHID + jbase + j];
    }

    // ---- per-thread h ownership: bloc=tid>>4, jp=(tid&15)*2 ----
    const int bloc = tid >> 4, jp = (tid & 15) * 2;
    const int bown = bbase + bloc;
    float2 al2 = *(const float2*)&alpha[jbase + jp];
    float2 bi2 = *(const float2*)&w_b[jbase + jp];
    float2 ns2 = make_float2(0.05f * sqrtf(al2.x), 0.05f * sqrtf(al2.y));
    const int pt = *ptp;
    float2 hv = *(const float2*)&hidden[(size_t)bown * NHID + jbase + jp];
    float h0 = hv.x, h1 = hv.y;
    {
        float a0 = fast_tanh(h0), a1 = fast_tanh(h1);
        __nv_bfloat16 h0b = __float2bfloat16(a0), h1b = __float2bfloat16(a1);
        __nv_bfloat16 l0b = __float2bfloat16(a0 - __bfloat162float(h0b));
        __nv_bfloat16 l1b = __float2bfloat16(a1 - __bfloat162float(h1b));
        size_t e = (size_t)bown * NHID + jbase + jp;
        *(uint32_t*)&g_abf[0][0][e] = (uint32_t)__bfloat16_as_ushort(h0b) | ((uint32_t)__bfloat16_as_ushort(h1b) << 16);
        *(uint32_t*)&g_abf[0][1][e] = (uint32_t)__bfloat16_as_ushort(l0b) | ((uint32_t)__bfloat16_as_ushort(l1b) << 16);
    }

    unsigned bar_t = *((volatile unsigned*)&g_release4[bg * 32]);
    __syncthreads();   // uniform bar_t snapshot before anyone arrives

    // ---- per-warp A ring (4 slots) + lane constants ----
    const uint32_t ring_u = smu + SMB_RING + (uint32_t)(w * 4096);
    const int spl = lane >> 4, srow = lane & 15;
    const int rb = bbase + mh * 16 + srow;
    const uint32_t sd0 = (uint32_t)(spl * 512 + srow * 32 + (((0) ^ ((srow >> 2) & 1)) << 4));
    const uint32_t sd1 = (uint32_t)(spl * 512 + srow * 32 + (((1) ^ ((srow >> 2) & 1)) << 4));
    const uint32_t a_off = (uint32_t)((lane & 15) * 32 + (((lane >> 4) ^ (((lane & 15) >> 2) & 1)) << 4));
    const int jb = ((lane >> 4) << 3) + (lane & 7);
    const int gplus = (lane >> 3) & 1;
    const uint32_t whi_u = smu + SMB_W, wlo_u = whi_u + WPLANE;

    const size_t arow = (size_t)rb * NHID + kq * 16;
    const __nv_bfloat16* xrowbase = g_xbf[spl] + (size_t)rb * NIN + kq * 16;

#define STG(SRC, SLOT) do { \
        uint32_t _d = ring_u + (uint32_t)((SLOT) * 1024); \
        cpa16(_d + sd0, (SRC)); cpa16(_d + sd1, (SRC) + 8); cpcommit(); } while (0)

    // pre-stage x(0) into slot 0
    STG(xrowbase, 0);
    GB_ARRIVE(); GB_WAIT();

    for (int t = 0; t < Tn; t++) {
        const int par = t & 1;
        const __nv_bfloat16* abase = g_abf[par][spl] + arow;

        // stage act chunks 0,1,2 into slots 1,2,3 (item m -> slot m&3)
        STG(abase, 1);
        STG(abase + 128, 2);
        STG(abase + 256, 3);

        float d[16];
        #pragma unroll
        for (int i = 0; i < 16; i++) d[i] = 0.f;

        #pragma unroll 1
        for (int n = 0; n < 9; n++) {
            if (n >= 1 && n <= 5) { STG(abase + (n + 2) * 128, (n - 1) & 3); cpwait<3>(); }
            else if (n == 0) cpwait<3>();
            else if (n == 6) cpwait<2>();
            else if (n == 7) cpwait<1>();
            else cpwait<0>();
            __syncwarp();

            const int ckb = ((n == 0) ? 1024 : (n - 1) * 128) + kq * 16;
            const uint32_t ab = ring_u + (uint32_t)((n & 3) * 1024) + a_off;
            uint32_t ah[4], al[4], bh[8], bl[8];
            LDM4(ah, ab);
            LDM4(al, ab + 512);
            {
                int gx = ((ckb >> 3) + gplus) ^ (lane & 7);
                uint32_t b0a = (uint32_t)(jb * 2304 + (gx << 4));
                LDM4(bh,     whi_u + b0a);
                LDM4(bh + 4, whi_u + b0a + 16 * 2304);
                LDM4(bl,     wlo_u + b0a);
                LDM4(bl + 4, wlo_u + b0a + 16 * 2304);
            }
            #pragma unroll
            for (int nt = 0; nt < 4; nt++) {
                HMMA(d + nt * 4, ah, bh[nt * 2], bh[nt * 2 + 1]);
                HMMA(d + nt * 4, ah, bl[nt * 2], bl[nt * 2 + 1]);
                HMMA(d + nt * 4, al, bh[nt * 2], bh[nt * 2 + 1]);
            }
        }
        __syncthreads();   // rings fully consumed (red aliases them)

        // ---- dump D partials to red[kq][b][34] ----
        {
            int babs = mh * 16 + (lane >> 2);
            #pragma unroll
            for (int nt = 0; nt < 4; nt++) {
                int j = nt * 8 + (lane & 3) * 2;
                *(float2*)&red[(kq * 32 + babs) * 34 + j]     = make_float2(d[nt*4+0], d[nt*4+1]);
                *(float2*)&red[(kq * 32 + babs + 8) * 34 + j] = make_float2(d[nt*4+2], d[nt*4+3]);
            }
        }
        __syncthreads();

        // ---- 8-way reduce + h update + g_act write ----
        {
            float s0 = bi2.x, s1 = bi2.y;
            #pragma unroll
            for (int g = 0; g < 8; g++) {
                float2 v = *(const float2*)&red[(g * 32 + bloc) * 34 + jp];
                s0 += v.x; s1 += v.y;
            }
            h0 = (1.f - al2.x) * h0 + al2.x * s0;
            h1 = (1.f - al2.y) * h1 + al2.y * s1;
            if (t == pt) {
                float2 n = *(const float2*)&noise[(size_t)bown * NHID + jbase + jp];
                h0 += n.x * ns2.x; h1 += n.y * ns2.y;
            }
        }
        *(float2*)&hb[bloc * 34 + jp] = make_float2(h0, h1);
        {
            float a0 = fast_tanh(h0), a1 = fast_tanh(h1);
            __nv_bfloat16 h0b = __float2bfloat16(a0), h1b = __float2bfloat16(a1);
            __nv_bfloat16 l0b = __float2bfloat16(a0 - __bfloat162float(h0b));
            __nv_bfloat16 l1b = __float2bfloat16(a1 - __bfloat162float(h1b));
            size_t e = (size_t)bown * NHID + jbase + jp;
            *(uint32_t*)&g_abf[par ^ 1][0][e] = (uint32_t)__bfloat16_as_ushort(h0b) | ((uint32_t)__bfloat16_as_ushort(h1b) << 16);
            *(uint32_t*)&g_abf[par ^ 1][1][e] = (uint32_t)__bfloat16_as_ushort(l0b) | ((uint32_t)__bfloat16_as_ushort(l1b) << 16);
        }

        // ARRIVE's internal syncthreads also publishes hb and finishes red reads
        GB_ARRIVE();

        // ======== shadow work during barrier skew ========
        // stage x(t+1) into ring slot 0 (red reads done at arrive's sync)
        if (t + 1 < Tn) STG(xrowbase + (size_t)(t + 1) * (128 * NIN), 0);
        // reduce out(t-2): issue LDGs early so latency overlaps the FFMA below
        float racc = 0.f; int re = 0;
        if (t >= 2 && lane < 4) {
            re = cta * 64 + w * 4 + lane;
            const float* src = g_outpart[(t - 2) % 3];
            #pragma unroll
            for (int r = 0; r < JGN; r++) racc += __ldcg(src + r * (Bn * NOUT) + re);
        }
        // hidden_list (+h_final) from regs
        {
            float2 v = make_float2(h0, h1);
            *(float2*)&out[OUT_HID + (size_t)bown * (Tn * NHID) + (size_t)t * NHID + jbase + jp] = v;
            if (t == Tn - 1)
                *(float2*)&out[OUT_HF + (size_t)bown * NHID + jbase + jp] = v;
        }
        // out partial GEMM
        {
            const int br = tid >> 4, o0 = (tid & 15) * 4;
            float oa0 = 0.f, oa1 = 0.f, oa2 = 0.f, oa3 = 0.f;
            #pragma unroll
            for (int j = 0; j < JSL; j++) {
                float a = hb[br * 34 + j];
                float4 w4 = *(const float4*)(wo_s + j * 64 + o0);
                oa0 += a * w4.x; oa1 += a * w4.y; oa2 += a * w4.z; oa3 += a * w4.w;
            }
            float* op = g_outpart[t % 3] + jg * (Bn * NOUT);
            *(float4*)&op[(bbase + br) * 64 + o0] = make_float4(oa0, oa1, oa2, oa3);
        }
        if (t >= 2 && lane < 4)
            out[OUT_OUT + (re >> 6) * (Tn * NOUT) + (t - 2) * NOUT + (re & 63)] = racc;

        GB_WAIT();
    }

    // ---- drain ----
    if (lane < 4) {
        int e = cta * 64 + w * 4 + lane;
        const float* src = g_outpart[(Tn - 2) % 3];
        float s = 0.f;
        #pragma unroll
        for (int r = 0; r < JGN; r++) s += __ldcg(src + r * (Bn * NOUT) + e);
        out[OUT_OUT + (e >> 6) * (Tn * NOUT) + (Tn - 2) * NOUT + (e & 63)] = s;
    }
    GB_ARRIVE(); GB_WAIT();
    if (lane < 4) {
        int e = cta * 64 + w * 4 + lane;
        const float* src = g_outpart[(Tn - 1) % 3];
        float s = 0.f;
        #pragma unroll
        for (int r = 0; r < JGN; r++) s += __ldcg(src + r * (Bn * NOUT) + e);
        out[OUT_OUT + (e >> 6) * (Tn * NOUT) + (Tn - 1) * NOUT + (e & 63)] = s;
    }
#undef STG
}
#undef GB_ARRIVE
#undef GB_WAIT

extern "C" void kernel_launch(void* const* d_in, const int* in_sizes, int n_in,
                              void* d_out, int out_size)
{
    const float* input_signal = (const float*)d_in[0];
    const float* hidden       = (const float*)d_in[1];
    const float* w_in_w       = (const float*)d_in[2];
    const float* w_hh_w       = (const float*)d_in[3];
    const float* w_hh_b       = (const float*)d_in[4];
    const float* w_out_w      = (const float*)d_in[5];
    const float* alpha        = (const float*)d_in[6];
    const float* noise_raw    = (const float*)d_in[7];
    const int*   pt           = (const int*)d_in[8];
    float* out = (float*)d_out;

    cudaFuncSetAttribute(rnn_main, cudaFuncAttributeMaxDynamicSharedMemorySize, SMEM_BYTES);
    xbf_kernel<<<2048, 512>>>(input_signal);
    rnn_main<<<NCTA, THREADS, SMEM_BYTES>>>(hidden, w_in_w, w_hh_w, w_hh_b,
                                            w_out_w, alpha, noise_raw, pt, out);
}